// round 13
// baseline (speedup 1.0000x reference)
#include <cuda_runtime.h>
#include <cuda_bf16.h>
#include <cuda_fp16.h>
#include <cstdint>

// FBGCN layer:
//   Hh = d_inv @ (lap @ (d_inv @ relu(x @ W_high)))  -- int8 2-digit split IMMA GEMMs
//   Hl = GCNConv(x, edge_index, W_conv, b_conv)      -- CSR gather (fp16 features)
//   out = aL*Hl + aH*Hh

static constexpr int N_NODES = 4096;
static constexpr int DIM     = 256;
static constexpr int N_EDGES = 131072;
static constexpr size_t NM   = (size_t)N_NODES * DIM;

// fp32 scratch
__device__ __align__(16) float g_A[NM];          // Hl
__device__ __align__(16) float g_P[8 * NM];      // 8 split partials (scaled fp32)
__device__ __align__(16) float g_Tf[NM];         // activation fp32 [256 x 4096]
__device__ __align__(16) __half g_XWh[NM];       // XW_conv fp16
__device__ float g_dis[N_NODES];
__device__ int   g_src[N_EDGES];
__device__ int   g_dst[N_EDGES];
__device__ int   g_is64;
// CSR
__device__ int   g_degi[N_NODES];
__device__ int   g_rowoff[N_NODES + 1];
__device__ int   g_cursor[N_NODES];
__device__ int   g_csr[N_EDGES];
// max scalars (static zero-init; atomicMax is idempotent across graph replays)
__device__ float g_maxDinv = 0.f;
__device__ float g_maxLap  = 0.f;
__device__ float g_maxR    = 0.f;
__device__ float g_maxT1   = 0.f;
__device__ float g_maxT2   = 0.f;

// int8 2-digit buffers
__device__ __align__(128) int8_t g_dinv_q1[(size_t)N_NODES * N_NODES];
__device__ __align__(128) int8_t g_dinv_q0[(size_t)N_NODES * N_NODES];
__device__ __align__(128) int8_t g_lap_q1 [(size_t)N_NODES * N_NODES];
__device__ __align__(128) int8_t g_lap_q0 [(size_t)N_NODES * N_NODES];
__device__ __align__(128) int8_t g_actq1[NM];    // activations^T [256 x 4096]
__device__ __align__(128) int8_t g_actq0[NM];

// bf16 buffers for the two small GEMMs
__device__ __align__(128) __nv_bfloat16 g_xhi[NM];
__device__ __align__(128) __nv_bfloat16 g_xlo[NM];
__device__ __align__(128) __nv_bfloat16 g_Wth[DIM * DIM];    // W_high^T splits
__device__ __align__(128) __nv_bfloat16 g_Wtl[DIM * DIM];
__device__ __align__(128) __nv_bfloat16 g_Wth2[DIM * DIM];   // W_conv^T splits
__device__ __align__(128) __nv_bfloat16 g_Wtl2[DIM * DIM];

// ---------------------------------------------------------------------------
// PTX helpers
// ---------------------------------------------------------------------------
__device__ __forceinline__ uint32_t smem_u32(const void* p) {
    uint32_t a;
    asm("{ .reg .u64 t; cvta.to.shared.u64 t, %1; cvt.u32.u64 %0, t; }" : "=r"(a) : "l"(p));
    return a;
}
__device__ __forceinline__ void cp_async16(uint32_t dst, const void* src) {
    asm volatile("cp.async.cg.shared.global [%0], [%1], 16;" :: "r"(dst), "l"(src) : "memory");
}
__device__ __forceinline__ void cp_commit() { asm volatile("cp.async.commit_group;" ::: "memory"); }
template <int N>
__device__ __forceinline__ void cp_wait() { asm volatile("cp.async.wait_group %0;" :: "n"(N) : "memory"); }

__device__ __forceinline__ void ldsm_x4(uint32_t* r, uint32_t addr) {
    asm volatile("ldmatrix.sync.aligned.m8n8.x4.shared.b16 {%0,%1,%2,%3}, [%4];"
        : "=r"(r[0]), "=r"(r[1]), "=r"(r[2]), "=r"(r[3]) : "r"(addr));
}
__device__ __forceinline__ void mma16816(float* c, const uint32_t* a, const uint32_t* b) {
    asm volatile("mma.sync.aligned.m16n8k16.row.col.f32.bf16.bf16.f32 "
        "{%0,%1,%2,%3}, {%4,%5,%6,%7}, {%8,%9}, {%0,%1,%2,%3};"
        : "+f"(c[0]), "+f"(c[1]), "+f"(c[2]), "+f"(c[3])
        : "r"(a[0]), "r"(a[1]), "r"(a[2]), "r"(a[3]), "r"(b[0]), "r"(b[1]));
}
__device__ __forceinline__ void mma_s8(int* c, const uint32_t* a, const uint32_t* b) {
    asm volatile("mma.sync.aligned.m16n8k32.row.col.s32.s8.s8.s32 "
        "{%0,%1,%2,%3}, {%4,%5,%6,%7}, {%8,%9}, {%0,%1,%2,%3};"
        : "+r"(c[0]), "+r"(c[1]), "+r"(c[2]), "+r"(c[3])
        : "r"(a[0]), "r"(a[1]), "r"(a[2]), "r"(a[3]), "r"(b[0]), "r"(b[1]));
}
__device__ __forceinline__ void atomic_fmax(float* addr, float v) {
    atomicMax((int*)addr, __float_as_int(v));   // v >= 0
}

// ---------------------------------------------------------------------------
// detect dtype + zero degree counters
// ---------------------------------------------------------------------------
__global__ void detect_init_kernel(const unsigned int* __restrict__ raw)
{
    int b = blockIdx.x;
    if (b == 0) {
        if (threadIdx.x == 0) {
            int is64 = 1;
            #pragma unroll 1
            for (int i = 0; i < 128; i++)
                if (raw[2 * i + 1] != 0u) { is64 = 0; break; }
            g_is64 = is64;
        }
    } else {
        g_degi[(b - 1) * 256 + threadIdx.x] = 0;
    }
}
__global__ void convert_edges_kernel(const void* __restrict__ rawp)
{
    int e = blockIdx.x * blockDim.x + threadIdx.x;
    if (e >= N_EDGES) return;
    int s, d;
    if (g_is64) {
        const long long* ei = (const long long*)rawp;
        s = (int)ei[e];
        d = (int)ei[N_EDGES + e];
    } else {
        const int* ei = (const int*)rawp;
        s = ei[e];
        d = ei[N_EDGES + e];
    }
    g_src[e] = s;
    g_dst[e] = d;
    atomicAdd(&g_degi[d], 1);
}

// ---------------------------------------------------------------------------
// max(|x|) reduction (atomicMax into scalar; scalar statically zero)
// ---------------------------------------------------------------------------
__global__ void maxabs_kernel(const float4* __restrict__ src, int n4, float* __restrict__ gmax)
{
    int id = blockIdx.x * blockDim.x + threadIdx.x;
    float m = 0.f;
    if (id < n4) {
        float4 v = src[id];
        m = fmaxf(fmaxf(fabsf(v.x), fabsf(v.y)), fmaxf(fabsf(v.z), fabsf(v.w)));
    }
    #pragma unroll
    for (int off = 16; off; off >>= 1)
        m = fmaxf(m, __shfl_xor_sync(0xFFFFFFFFu, m, off));
    if ((threadIdx.x & 31) == 0) atomic_fmax(gmax, m);
}

// ---------------------------------------------------------------------------
// int8 2-digit quantization: a ~= (max/127)*(q1 + q0/256)
// ---------------------------------------------------------------------------
__global__ void quant_kernel(const float4* __restrict__ src,
                             char4* __restrict__ q1, char4* __restrict__ q0,
                             int n4, const float* __restrict__ maxp)
{
    int id = blockIdx.x * blockDim.x + threadIdx.x;
    if (id >= n4) return;
    float mx   = fmaxf(maxp[0], 1e-30f);
    float inv  = 127.f / mx;
    float step = mx * (1.f / 127.f);
    float4 v = src[id];
    float f[4] = { v.x, v.y, v.z, v.w };
    char a1[4], a0[4];
    #pragma unroll
    for (int i = 0; i < 4; i++) {
        int h = __float2int_rn(f[i] * inv);
        h = max(-127, min(127, h));
        float r = f[i] - (float)h * step;
        int l = __float2int_rn(r * inv * 256.f);
        l = max(-127, min(127, l));
        a1[i] = (char)h; a0[i] = (char)l;
    }
    q1[id] = make_char4(a1[0], a1[1], a1[2], a1[3]);
    q0[id] = make_char4(a0[0], a0[1], a0[2], a0[3]);
}

// ---------------------------------------------------------------------------
// W [256 x 256] fp32 row-major -> W^T bf16 splits [256 x 256]
// ---------------------------------------------------------------------------
__global__ void wtranspose_split_kernel(const float* __restrict__ W,
                                        __nv_bfloat16* __restrict__ hi,
                                        __nv_bfloat16* __restrict__ lo)
{
    __shared__ float tile[32][33];
    int k0 = blockIdx.x * 32;
    int n0 = blockIdx.y * 32;
    int tx = threadIdx.x, ty = threadIdx.y;    // 32 x 8
    #pragma unroll
    for (int j = 0; j < 4; j++)
        tile[ty + j * 8][tx] = W[(size_t)(k0 + ty + j * 8) * DIM + n0 + tx];
    __syncthreads();
    #pragma unroll
    for (int j = 0; j < 4; j++) {
        int n = ty + j * 8;
        float v = tile[tx][n];
        __nv_bfloat16 h = __float2bfloat16(v);
        __nv_bfloat16 l = __float2bfloat16(v - __bfloat162float(h));
        size_t o = (size_t)(n0 + n) * DIM + k0 + tx;
        hi[o] = h; lo[o] = l;
    }
}

// fp32 -> bf16 hi/lo split (x)
__global__ void split_kernel(const float4* __restrict__ src,
                             uint4* __restrict__ hi, uint4* __restrict__ lo, int n8)
{
    int id = blockIdx.x * blockDim.x + threadIdx.x;
    if (id >= n8) return;
    float4 a = src[2 * id], b = src[2 * id + 1];
    float f[8] = { a.x, a.y, a.z, a.w, b.x, b.y, b.z, b.w };
    uint32_t H[4], L[4];
    #pragma unroll
    for (int i = 0; i < 4; i++) {
        __nv_bfloat16 h0 = __float2bfloat16(f[2 * i + 0]);
        __nv_bfloat16 h1 = __float2bfloat16(f[2 * i + 1]);
        __nv_bfloat16 l0 = __float2bfloat16(f[2 * i + 0] - __bfloat162float(h0));
        __nv_bfloat16 l1 = __float2bfloat16(f[2 * i + 1] - __bfloat162float(h1));
        __nv_bfloat162 hh(h0, h1), ll(l0, l1);
        H[i] = *(uint32_t*)&hh;
        L[i] = *(uint32_t*)&ll;
    }
    hi[id] = make_uint4(H[0], H[1], H[2], H[3]);
    lo[id] = make_uint4(L[0], L[1], L[2], L[3]);
}

// ---------------------------------------------------------------------------
// bf16 mma.sync GEMM (small GEMMs only). CTA 128x128, BK=64, 4 warps 64x64.
// OUT_MODE 1: fp16 out (XW_conv). OUT_MODE 3: fp32 out + atomicMax (R^T, RELU).
// ---------------------------------------------------------------------------
static constexpr int STAGES   = 3;
static constexpr int ROWB     = 144;
static constexpr int A_BYTES  = 128 * ROWB;
static constexpr int STAGE_B  = 2 * A_BYTES;
static constexpr int GEMM_SMEM = STAGES * STAGE_B;    // 110592

template <bool RELU, int OUT_MODE>
__global__ __launch_bounds__(128, 2) void gemm_bf16_kernel(
    const __nv_bfloat16* __restrict__ Ahi, const __nv_bfloat16* __restrict__ Alo,
    const __nv_bfloat16* __restrict__ Bhi, const __nv_bfloat16* __restrict__ Blo,
    __half* __restrict__ Ch, float* __restrict__ Cf, float* __restrict__ gmax,
    int strideA, int strideB, int strideC, int nit, int segShift)
{
    extern __shared__ char smem[];
    const uint32_t sbase = smem_u32(smem);
    const int t    = threadIdx.x;
    const int lane = t & 31;
    const int wid  = t >> 5;
    const int wm   = wid >> 1;
    const int wn   = wid & 1;
    const int m0   = blockIdx.y * 128;
    const int n0   = blockIdx.x * 128;
    const int segMask = (1 << segShift) - 1;

    const __nv_bfloat16* Aseg[3] = { Ahi, Ahi, Alo };
    const __nv_bfloat16* Bseg[3] = { Bhi, Blo, Bhi };

    const int rowBase = t >> 3;
    const int ch      = t & 7;
    uint32_t aOffG[8], bOffG[8], sOffA[8];
    #pragma unroll
    for (int i = 0; i < 8; i++) {
        int row = rowBase + 16 * i;
        aOffG[i] = (uint32_t)((m0 + row) * strideA + ch * 8);
        bOffG[i] = (uint32_t)((n0 + row) * strideB + ch * 8);
        sOffA[i] = (uint32_t)(row * ROWB + ch * 16);
    }
    const uint32_t aLd = (uint32_t)(wm * 64 + (lane & 15)) * ROWB + (lane >> 4) * 16;
    const uint32_t bLd = A_BYTES +
        (uint32_t)(wn * 64 + ((lane >> 4) & 1) * 8 + (lane & 7)) * ROWB + ((lane >> 3) & 1) * 16;

    float acc[4][8][4];
    #pragma unroll
    for (int f = 0; f < 4; f++)
        #pragma unroll
        for (int j = 0; j < 8; j++)
            #pragma unroll
            for (int e = 0; e < 4; e++) acc[f][j][e] = 0.f;

    auto load_stage = [&](int ci, int s) {
        if (ci < nit) {
            int seg = ci >> segShift;
            int k0  = (ci & segMask) << 6;
            const __nv_bfloat16* ap = Aseg[seg] + k0;
            const __nv_bfloat16* bp = Bseg[seg] + k0;
            uint32_t sb = sbase + s * STAGE_B;
            #pragma unroll
            for (int i = 0; i < 8; i++) cp_async16(sb + sOffA[i], ap + aOffG[i]);
            #pragma unroll
            for (int i = 0; i < 8; i++) cp_async16(sb + A_BYTES + sOffA[i], bp + bOffG[i]);
        }
        cp_commit();
    };

    load_stage(0, 0);
    load_stage(1, 1);

    for (int ci = 0; ci < nit; ci++) {
        cp_wait<STAGES - 2>();
        __syncthreads();
        load_stage(ci + STAGES - 1, (ci + STAGES - 1) % STAGES);

        uint32_t sb = sbase + (ci % STAGES) * STAGE_B;
        #pragma unroll
        for (int ks = 0; ks < 4; ks++) {
            uint32_t a[4][4], b[4][4];
            #pragma unroll
            for (int f = 0; f < 4; f++)
                ldsm_x4(a[f], sb + aLd + f * 16 * ROWB + ks * 32);
            #pragma unroll
            for (int g = 0; g < 4; g++)
                ldsm_x4(b[g], sb + bLd + g * 16 * ROWB + ks * 32);
            #pragma unroll
            for (int f = 0; f < 4; f++)
                #pragma unroll
                for (int g = 0; g < 4; g++) {
                    mma16816(acc[f][2 * g + 0], a[f], &b[g][0]);
                    mma16816(acc[f][2 * g + 1], a[f], &b[g][2]);
                }
        }
    }

    const int gid = lane >> 2;
    const int tig = lane & 3;
    float wmax = 0.f;
    #pragma unroll
    for (int f = 0; f < 4; f++) {
        int rbase = m0 + wm * 64 + f * 16 + gid;
        #pragma unroll
        for (int j = 0; j < 8; j++) {
            int col = n0 + wn * 64 + j * 8 + tig * 2;
            float2 v0 = { acc[f][j][0], acc[f][j][1] };
            float2 v1 = { acc[f][j][2], acc[f][j][3] };
            if (RELU) {
                v0.x = fmaxf(v0.x, 0.f); v0.y = fmaxf(v0.y, 0.f);
                v1.x = fmaxf(v1.x, 0.f); v1.y = fmaxf(v1.y, 0.f);
            }
            size_t o0 = (size_t)rbase * strideC + col;
            size_t o1 = (size_t)(rbase + 8) * strideC + col;
            if (OUT_MODE == 1) {
                __half2* Hp = (__half2*)Ch;
                Hp[o0 >> 1] = __floats2half2_rn(v0.x, v0.y);
                Hp[o1 >> 1] = __floats2half2_rn(v1.x, v1.y);
            } else {
                *reinterpret_cast<float2*>(Cf + o0) = v0;
                *reinterpret_cast<float2*>(Cf + o1) = v1;
                wmax = fmaxf(wmax, fmaxf(fmaxf(fabsf(v0.x), fabsf(v0.y)),
                                         fmaxf(fabsf(v1.x), fabsf(v1.y))));
            }
        }
    }
    if (OUT_MODE == 3) {
        #pragma unroll
        for (int off = 16; off; off >>= 1)
            wmax = fmaxf(wmax, __shfl_xor_sync(0xFFFFFFFFu, wmax, off));
        if (lane == 0) atomic_fmax(gmax, wmax);
    }
}

// ---------------------------------------------------------------------------
// int8 IMMA GEMM: C[4096 x 256] = A[4096 x 4096] @ act^T[256 x 4096]^T
// 2-digit split over blockIdx.z in [0, 8):
//   z 0-3: q1A.q1B, K quarters (1024), scale s
//   z 4-5: q1A.q0B, K halves (2048),  scale s/256
//   z 6-7: q0A.q1B, K halves (2048),  scale s/256
// CTA 128x128, BK=128 int8 (128B rows, same smem geometry as bf16 kernel).
// ---------------------------------------------------------------------------
__global__ __launch_bounds__(128, 2) void gemm_s8_kernel(
    const int8_t* __restrict__ Aq1, const int8_t* __restrict__ Aq0,
    const int8_t* __restrict__ Bq1, const int8_t* __restrict__ Bq0,
    const float* __restrict__ maxAp, const float* __restrict__ maxBp,
    float* __restrict__ P)
{
    extern __shared__ char smem[];
    const uint32_t sbase = smem_u32(smem);
    const int t    = threadIdx.x;
    const int lane = t & 31;
    const int wid  = t >> 5;
    const int wm   = wid >> 1;
    const int wn   = wid & 1;
    const int m0   = blockIdx.y * 128;
    const int n0   = blockIdx.x * 128;
    const int z    = blockIdx.z;

    const int8_t* Ab; const int8_t* Bb; int k0, nit; float sdiv;
    if (z < 4)      { Ab = Aq1; Bb = Bq1; k0 = z * 1024;       nit = 8;  sdiv = 1.f; }
    else if (z < 6) { Ab = Aq1; Bb = Bq0; k0 = (z - 4) * 2048; nit = 16; sdiv = 1.f / 256.f; }
    else            { Ab = Aq0; Bb = Bq1; k0 = (z - 6) * 2048; nit = 16; sdiv = 1.f / 256.f; }

    const int rowBase = t >> 3;
    const int ch      = t & 7;
    uint32_t aG[8], bG[8], sO[8];
    #pragma unroll
    for (int i = 0; i < 8; i++) {
        int row = rowBase + 16 * i;
        aG[i] = (uint32_t)((m0 + row) * N_NODES + k0 + ch * 16);
        bG[i] = (uint32_t)((n0 + row) * N_NODES + k0 + ch * 16);
        sO[i] = (uint32_t)(row * ROWB + ch * 16);
    }
    const uint32_t aLd = (uint32_t)(wm * 64 + (lane & 15)) * ROWB + (lane >> 4) * 16;
    const uint32_t bLd = A_BYTES +
        (uint32_t)(wn * 64 + ((lane >> 4) & 1) * 8 + (lane & 7)) * ROWB + ((lane >> 3) & 1) * 16;

    int acc[4][8][4];
    #pragma unroll
    for (int f = 0; f < 4; f++)
        #pragma unroll
        for (int j = 0; j < 8; j++)
            #pragma unroll
            for (int e = 0; e < 4; e++) acc[f][j][e] = 0;

    auto load_stage = [&](int ci, int s) {
        if (ci < nit) {
            uint32_t off = (uint32_t)ci * 128;
            uint32_t sb = sbase + s * STAGE_B;
            #pragma unroll
            for (int i = 0; i < 8; i++) cp_async16(sb + sO[i], Ab + aG[i] + off);
            #pragma unroll
            for (int i = 0; i < 8; i++) cp_async16(sb + A_BYTES + sO[i], Bb + bG[i] + off);
        }
        cp_commit();
    };

    load_stage(0, 0);
    load_stage(1, 1);

    for (int ci = 0; ci < nit; ci++) {
        cp_wait<STAGES - 2>();
        __syncthreads();
        load_stage(ci + STAGES - 1, (ci + STAGES - 1) % STAGES);

        uint32_t sb = sbase + (ci % STAGES) * STAGE_B;
        #pragma unroll
        for (int ks = 0; ks < 4; ks++) {     // 4 x k32 = 128 int8
            uint32_t a[4][4], b[4][4];
            #pragma unroll
            for (int f = 0; f < 4; f++)
                ldsm_x4(a[f], sb + aLd + f * 16 * ROWB + ks * 32);
            #pragma unroll
            for (int g = 0; g < 4; g++)
                ldsm_x4(b[g], sb + bLd + g * 16 * ROWB + ks * 32);
            #pragma unroll
            for (int f = 0; f < 4; f++)
                #pragma unroll
                for (int g = 0; g < 4; g++) {
                    mma_s8(acc[f][2 * g + 0], a[f], &b[g][0]);
                    mma_s8(acc[f][2 * g + 1], a[f], &b[g][2]);
                }
        }
    }

    float s = (maxAp[0] * (1.f / 127.f)) * (maxBp[0] * (1.f / 127.f)) * sdiv;
    float* C = P + (size_t)z * NM;
    const int gid = lane >> 2;
    const int tig = lane & 3;
    #pragma unroll
    for (int f = 0; f < 4; f++) {
        int rbase = m0 + wm * 64 + f * 16 + gid;
        #pragma unroll
        for (int j = 0; j < 8; j++) {
            int col = n0 + wn * 64 + j * 8 + tig * 2;
            float2 v0 = { acc[f][j][0] * s, acc[f][j][1] * s };
            float2 v1 = { acc[f][j][2] * s, acc[f][j][3] * s };
            *reinterpret_cast<float2*>(C + (size_t)rbase * DIM + col) = v0;
            *reinterpret_cast<float2*>(C + (size_t)(rbase + 8) * DIM + col) = v1;
        }
    }
}

// ---------------------------------------------------------------------------
// sum 8 partials [4096 x 256] -> fp32 transposed [256 x 4096] + max
// ---------------------------------------------------------------------------
__global__ void sum8t_kernel(const float* __restrict__ P,
                             float* __restrict__ Tf, float* __restrict__ gmax)
{
    __shared__ float tile[32][33];
    int k0 = blockIdx.x * 32;     // node dim
    int n0 = blockIdx.y * 32;     // feature dim
    int tx = threadIdx.x, ty = threadIdx.y;    // 32 x 8
    #pragma unroll
    for (int j = 0; j < 4; j++) {
        size_t o = (size_t)(k0 + ty + j * 8) * DIM + n0 + tx;
        float v = ((P[o] + P[NM + o]) + (P[2 * NM + o] + P[3 * NM + o]))
                + ((P[4 * NM + o] + P[5 * NM + o]) + (P[6 * NM + o] + P[7 * NM + o]));
        tile[ty + j * 8][tx] = v;
    }
    __syncthreads();
    float lmax = 0.f;
    #pragma unroll
    for (int j = 0; j < 4; j++) {
        int n = ty + j * 8;
        float v = tile[tx][n];
        Tf[(size_t)(n0 + n) * N_NODES + k0 + tx] = v;
        lmax = fmaxf(lmax, fabsf(v));
    }
    #pragma unroll
    for (int off = 16; off; off >>= 1)
        lmax = fmaxf(lmax, __shfl_xor_sync(0xFFFFFFFFu, lmax, off));
    if ((threadIdx.x & 31) == 0) atomic_fmax(gmax, lmax);
}

// ---------------------------------------------------------------------------
// CSR build
// ---------------------------------------------------------------------------
__global__ __launch_bounds__(1024) void csr_scan_kernel()
{
    __shared__ int part[1024];
    int t = threadIdx.x;
    int v0 = g_degi[4 * t + 0], v1 = g_degi[4 * t + 1];
    int v2 = g_degi[4 * t + 2], v3 = g_degi[4 * t + 3];
    int s1 = v0 + v1, s2 = s1 + v2, s3 = s2 + v3;
    part[t] = s3;
    __syncthreads();
    #pragma unroll
    for (int off = 1; off < 1024; off <<= 1) {
        int x = (t >= off) ? part[t - off] : 0;
        __syncthreads();
        part[t] += x;
        __syncthreads();
    }
    int base = t ? part[t - 1] : 0;
    g_rowoff[4 * t + 0] = base;
    g_rowoff[4 * t + 1] = base + v0;
    g_rowoff[4 * t + 2] = base + s1;
    g_rowoff[4 * t + 3] = base + s2;
    if (t == 1023) g_rowoff[4096] = base + s3;
    #pragma unroll
    for (int i = 0; i < 4; i++) {
        int n = 4 * t + i;
        int d = g_degi[n];
        g_dis[n] = rsqrtf((float)(d + 1));
        g_cursor[n] = 0;
    }
}
__global__ void csr_place_kernel()
{
    int e = blockIdx.x * blockDim.x + threadIdx.x;
    if (e >= N_EDGES) return;
    int dst = g_dst[e];
    int pos = g_rowoff[dst] + atomicAdd(&g_cursor[dst], 1);
    g_csr[pos] = g_src[e];
}

// ---------------------------------------------------------------------------
// Gather: Hl -> g_A (side stream)
// ---------------------------------------------------------------------------
__global__ __launch_bounds__(128) void gather_kernel()
{
    int dst = blockIdx.x;
    int t   = threadIdx.x;
    const __half2* XW = (const __half2*)g_XWh;
    float disD = g_dis[dst];
    float2 sv = __half22float2(XW[(size_t)dst * 128 + t]);
    float accx = sv.x * disD * disD;
    float accy = sv.y * disD * disD;
    int beg = g_rowoff[dst], end = g_rowoff[dst + 1];
    int j = beg;
    for (; j + 1 < end; j += 2) {
        int s0 = g_csr[j], s1 = g_csr[j + 1];
        float w0 = g_dis[s0] * disD, w1 = g_dis[s1] * disD;
        float2 v0 = __half22float2(XW[(size_t)s0 * 128 + t]);
        float2 v1 = __half22float2(XW[(size_t)s1 * 128 + t]);
        accx += v0.x * w0 + v1.x * w1;
        accy += v0.y * w0 + v1.y * w1;
    }
    if (j < end) {
        int s0 = g_csr[j];
        float w0 = g_dis[s0] * disD;
        float2 v0 = __half22float2(XW[(size_t)s0 * 128 + t]);
        accx += v0.x * w0;
        accy += v0.y * w0;
    }
    *reinterpret_cast<float2*>(g_A + (size_t)dst * DIM + 2 * t) = make_float2(accx, accy);
}

// out = aL*(Hl + b) + aH*sum(P0..P7)
__global__ void combine_kernel(float* __restrict__ out,
                               const float* __restrict__ b,
                               const float* __restrict__ aLp,
                               const float* __restrict__ aHp)
{
    int id = blockIdx.x * blockDim.x + threadIdx.x;
    if (id >= (int)(NM / 4)) return;
    float aL = aLp[0], aH = aHp[0];
    int c4 = (id & (DIM / 4 - 1)) << 2;
    float4 hl = reinterpret_cast<const float4*>(g_A)[id];
    float4 hh = make_float4(0.f, 0.f, 0.f, 0.f);
    #pragma unroll
    for (int q = 0; q < 8; q++) {
        float4 p = reinterpret_cast<const float4*>(g_P + (size_t)q * NM)[id];
        hh.x += p.x; hh.y += p.y; hh.z += p.z; hh.w += p.w;
    }
    float4 bb = *reinterpret_cast<const float4*>(b + c4);
    float4 r;
    r.x = aL * (hl.x + bb.x) + aH * hh.x;
    r.y = aL * (hl.y + bb.y) + aH * hh.y;
    r.z = aL * (hl.z + bb.z) + aH * hh.z;
    r.w = aL * (hl.w + bb.w) + aH * hh.w;
    reinterpret_cast<float4*>(out)[id] = r;
}

// ---------------------------------------------------------------------------
extern "C" void kernel_launch(void* const* d_in, const int* in_sizes, int n_in,
                              void* d_out, int out_size)
{
    const float* x      = (const float*)d_in[0];
    const void*  ei_raw = d_in[1];
    const float* lap    = (const float*)d_in[2];
    const float* d_inv  = (const float*)d_in[3];
    const float* W_high = (const float*)d_in[4];
    const float* W_conv = (const float*)d_in[5];
    const float* b_conv = (const float*)d_in[6];
    const float* aL     = (const float*)d_in[7];
    const float* aH     = (const float*)d_in[8];
    float*       out    = (float*)d_out;

    float *pP, *pTf;
    cudaGetSymbolAddress((void**)&pP,  g_P);
    cudaGetSymbolAddress((void**)&pTf, g_Tf);
    __half* pXWh;
    cudaGetSymbolAddress((void**)&pXWh, g_XWh);
    int8_t *pDq1, *pDq0, *pLq1, *pLq0, *pAq1, *pAq0;
    cudaGetSymbolAddress((void**)&pDq1, g_dinv_q1);
    cudaGetSymbolAddress((void**)&pDq0, g_dinv_q0);
    cudaGetSymbolAddress((void**)&pLq1, g_lap_q1);
    cudaGetSymbolAddress((void**)&pLq0, g_lap_q0);
    cudaGetSymbolAddress((void**)&pAq1, g_actq1);
    cudaGetSymbolAddress((void**)&pAq0, g_actq0);
    float *pMD, *pML, *pMR, *pM1, *pM2;
    cudaGetSymbolAddress((void**)&pMD, g_maxDinv);
    cudaGetSymbolAddress((void**)&pML, g_maxLap);
    cudaGetSymbolAddress((void**)&pMR, g_maxR);
    cudaGetSymbolAddress((void**)&pM1, g_maxT1);
    cudaGetSymbolAddress((void**)&pM2, g_maxT2);
    __nv_bfloat16 *pXh, *pXl, *pWh, *pWl, *pWh2, *pWl2;
    cudaGetSymbolAddress((void**)&pXh, g_xhi);
    cudaGetSymbolAddress((void**)&pXl, g_xlo);
    cudaGetSymbolAddress((void**)&pWh, g_Wth);
    cudaGetSymbolAddress((void**)&pWl, g_Wtl);
    cudaGetSymbolAddress((void**)&pWh2, g_Wth2);
    cudaGetSymbolAddress((void**)&pWl2, g_Wtl2);

    cudaFuncSetAttribute(gemm_bf16_kernel<false, 1>, cudaFuncAttributeMaxDynamicSharedMemorySize, GEMM_SMEM);
    cudaFuncSetAttribute(gemm_bf16_kernel<true,  3>, cudaFuncAttributeMaxDynamicSharedMemorySize, GEMM_SMEM);
    cudaFuncSetAttribute(gemm_s8_kernel, cudaFuncAttributeMaxDynamicSharedMemorySize, GEMM_SMEM);

    cudaStream_t s1, s2;
    cudaStreamCreateWithFlags(&s1, cudaStreamNonBlocking);
    cudaStreamCreateWithFlags(&s2, cudaStreamNonBlocking);
    cudaEvent_t E0, Ex, Ed, El, Eg;
    cudaEventCreateWithFlags(&E0, cudaEventDisableTiming);
    cudaEventCreateWithFlags(&Ex, cudaEventDisableTiming);
    cudaEventCreateWithFlags(&Ed, cudaEventDisableTiming);
    cudaEventCreateWithFlags(&El, cudaEventDisableTiming);
    cudaEventCreateWithFlags(&Eg, cudaEventDisableTiming);

    dim3 gBig(DIM / 128, N_NODES / 128, 8);    // (2, 32, 8) int8 GEMM
    dim3 gRT (N_NODES / 128, DIM / 128, 1);    // (32, 2)    R^T bf16
    dim3 gSm (DIM / 128, N_NODES / 128, 1);    // (2, 32)    XW_conv bf16
    dim3 gSum(N_NODES / 32, DIM / 32);
    dim3 bTr(32, 8);
    dim3 gWt(DIM / 32, DIM / 32);
    const int NIT_SM = 3 * DIM / 64;           // 12
    const int SEG_SM = 2;
    int nbig4 = (int)((size_t)N_NODES * N_NODES / 4);   // 4194304
    int nact4 = (int)(NM / 4);                          // 262144
    int nx8   = (int)(NM / 8);

    // ---- fork ----
    cudaEventRecord(E0, 0);
    cudaStreamWaitEvent(s1, E0, 0);
    cudaStreamWaitEvent(s2, E0, 0);

    // s1: quantize big matrices (max then 2-digit int8)
    maxabs_kernel<<<nbig4 / 256, 256, 0, s1>>>((const float4*)d_inv, nbig4, pMD);
    quant_kernel <<<nbig4 / 256, 256, 0, s1>>>((const float4*)d_inv, (char4*)pDq1, (char4*)pDq0, nbig4, pMD);
    cudaEventRecord(Ed, s1);
    maxabs_kernel<<<nbig4 / 256, 256, 0, s1>>>((const float4*)lap, nbig4, pML);
    quant_kernel <<<nbig4 / 256, 256, 0, s1>>>((const float4*)lap, (char4*)pLq1, (char4*)pLq0, nbig4, pML);
    cudaEventRecord(El, s1);

    // s2: edges + CSR + W_conv; then XW_conv GEMM + gather
    detect_init_kernel  <<<17, 256, 0, s2>>>((const unsigned int*)ei_raw);
    convert_edges_kernel<<<N_EDGES / 256, 256, 0, s2>>>(ei_raw);
    csr_scan_kernel     <<<1, 1024, 0, s2>>>();
    csr_place_kernel    <<<N_EDGES / 256, 256, 0, s2>>>();
    wtranspose_split_kernel<<<gWt, bTr, 0, s2>>>(W_conv, pWh2, pWl2);

    // s0: prologue
    wtranspose_split_kernel<<<gWt, bTr>>>(W_high, pWh, pWl);
    split_kernel<<<nx8 / 256, 256>>>((const float4*)x, (uint4*)pXh, (uint4*)pXl, nx8);
    cudaEventRecord(Ex, 0);

    cudaStreamWaitEvent(s2, Ex, 0);
    gemm_bf16_kernel<false, 1><<<gSm, 128, GEMM_SMEM, s2>>>(pXh, pXl, pWh2, pWl2,
        pXWh, nullptr, nullptr, DIM, DIM, DIM, NIT_SM, SEG_SM);
    gather_kernel<<<N_NODES, 128, 0, s2>>>();
    cudaEventRecord(Eg, s2);

    // s0: R^T = relu(W_high^T @ x^T) -> fp32 [256 x 4096] + maxR; quantize
    gemm_bf16_kernel<true, 3><<<gRT, 128, GEMM_SMEM>>>(pWh, pWl, pXh, pXl,
        nullptr, pTf, pMR, DIM, DIM, N_NODES, NIT_SM, SEG_SM);
    quant_kernel<<<nact4 / 256, 256>>>((const float4*)pTf, (char4*)pAq1, (char4*)pAq0, nact4, pMR);
    // T1 = d_inv @ R
    cudaStreamWaitEvent(0, Ed, 0);
    gemm_s8_kernel<<<gBig, 128, GEMM_SMEM>>>(pDq1, pDq0, pAq1, pAq0, pMD, pMR, pP);
    sum8t_kernel<<<gSum, bTr>>>(pP, pTf, pM1);
    quant_kernel<<<nact4 / 256, 256>>>((const float4*)pTf, (char4*)pAq1, (char4*)pAq0, nact4, pM1);
    // T2 = lap @ T1
    cudaStreamWaitEvent(0, El, 0);
    gemm_s8_kernel<<<gBig, 128, GEMM_SMEM>>>(pLq1, pLq0, pAq1, pAq0, pML, pM1, pP);
    sum8t_kernel<<<gSum, bTr>>>(pP, pTf, pM2);
    quant_kernel<<<nact4 / 256, 256>>>((const float4*)pTf, (char4*)pAq1, (char4*)pAq0, nact4, pM2);
    // Hh = d_inv @ T2 (partials stay in g_P)
    gemm_s8_kernel<<<gBig, 128, GEMM_SMEM>>>(pDq1, pDq0, pAq1, pAq0, pMD, pM2, pP);

    // join + combine
    cudaStreamWaitEvent(0, Eg, 0);
    combine_kernel<<<(int)(NM / 4 + 255) / 256, 256>>>(out, b_conv, aL, aH);

    cudaEventDestroy(E0); cudaEventDestroy(Ex); cudaEventDestroy(Ed);
    cudaEventDestroy(El); cudaEventDestroy(Eg);
    cudaStreamDestroy(s1); cudaStreamDestroy(s2);
}

// round 14
// speedup vs baseline: 2.7009x; 2.7009x over previous
#include <cuda_runtime.h>
#include <cuda_bf16.h>
#include <cuda_fp16.h>
#include <cstdint>

// FBGCN layer:
//   Hh = d_inv @ (lap @ (d_inv @ relu(x @ W_high)))  -- mma.sync bf16-split GEMMs
//   Hl = GCNConv(x, edge_index, W_conv, b_conv)      -- CSR gather (fp16 features)
//   out = aL*Hl + aH*Hh
// Multi-stream overlap; final combine fused into GEMM3's atomic epilogue.

static constexpr int N_NODES = 4096;
static constexpr int DIM     = 256;
static constexpr int N_EDGES = 131072;

// fp32 scratch
__device__ __align__(16) float g_A[N_NODES * DIM];    // Hl
__device__ __align__(16) float g_P0[N_NODES * DIM];   // split-K partials
__device__ __align__(16) float g_P1[N_NODES * DIM];
__device__ __align__(16) float g_P2[N_NODES * DIM];
__device__ __align__(16) float g_P3[N_NODES * DIM];
__device__ __align__(16) __half g_XWh[N_NODES * DIM]; // XW_conv in fp16
__device__ float g_dis[N_NODES];
__device__ int   g_src[N_EDGES];
__device__ int   g_dst[N_EDGES];
__device__ int   g_is64;
// CSR
__device__ int   g_degi[N_NODES];
__device__ int   g_rowoff[N_NODES + 1];
__device__ int   g_cursor[N_NODES];
__device__ int   g_csr[N_EDGES];

// bf16 split buffers
__device__ __align__(128) __nv_bfloat16 g_dinv_hi[N_NODES * N_NODES];
__device__ __align__(128) __nv_bfloat16 g_dinv_lo[N_NODES * N_NODES];
__device__ __align__(128) __nv_bfloat16 g_lap_hi [N_NODES * N_NODES];
__device__ __align__(128) __nv_bfloat16 g_lap_lo [N_NODES * N_NODES];
__device__ __align__(128) __nv_bfloat16 g_Bhi[DIM * N_NODES];   // [256 x 4096] act^T
__device__ __align__(128) __nv_bfloat16 g_Blo[DIM * N_NODES];
__device__ __align__(128) __nv_bfloat16 g_xhi[N_NODES * DIM];   // x splits (K-major rows)
__device__ __align__(128) __nv_bfloat16 g_xlo[N_NODES * DIM];
__device__ __align__(128) __nv_bfloat16 g_Wth[DIM * DIM];       // W_high^T splits
__device__ __align__(128) __nv_bfloat16 g_Wtl[DIM * DIM];
__device__ __align__(128) __nv_bfloat16 g_Wth2[DIM * DIM];      // W_conv^T splits
__device__ __align__(128) __nv_bfloat16 g_Wtl2[DIM * DIM];

// ---------------------------------------------------------------------------
// PTX helpers
// ---------------------------------------------------------------------------
__device__ __forceinline__ uint32_t smem_u32(const void* p) {
    uint32_t a;
    asm("{ .reg .u64 t; cvta.to.shared.u64 t, %1; cvt.u32.u64 %0, t; }" : "=r"(a) : "l"(p));
    return a;
}
__device__ __forceinline__ void cp_async16(uint32_t dst, const void* src) {
    asm volatile("cp.async.cg.shared.global [%0], [%1], 16;" :: "r"(dst), "l"(src) : "memory");
}
__device__ __forceinline__ void cp_commit() { asm volatile("cp.async.commit_group;" ::: "memory"); }
template <int N>
__device__ __forceinline__ void cp_wait() { asm volatile("cp.async.wait_group %0;" :: "n"(N) : "memory"); }

__device__ __forceinline__ void ldsm_x4(uint32_t* r, uint32_t addr) {
    asm volatile("ldmatrix.sync.aligned.m8n8.x4.shared.b16 {%0,%1,%2,%3}, [%4];"
        : "=r"(r[0]), "=r"(r[1]), "=r"(r[2]), "=r"(r[3]) : "r"(addr));
}
__device__ __forceinline__ void mma16816(float* c, const uint32_t* a, const uint32_t* b) {
    asm volatile("mma.sync.aligned.m16n8k16.row.col.f32.bf16.bf16.f32 "
        "{%0,%1,%2,%3}, {%4,%5,%6,%7}, {%8,%9}, {%0,%1,%2,%3};"
        : "+f"(c[0]), "+f"(c[1]), "+f"(c[2]), "+f"(c[3])
        : "r"(a[0]), "r"(a[1]), "r"(a[2]), "r"(a[3]), "r"(b[0]), "r"(b[1]));
}

// ---------------------------------------------------------------------------
// detect dtype + zero degree counters
// ---------------------------------------------------------------------------
__global__ void detect_init_kernel(const unsigned int* __restrict__ raw)
{
    int b = blockIdx.x;
    if (b == 0) {
        if (threadIdx.x == 0) {
            int is64 = 1;
            #pragma unroll 1
            for (int i = 0; i < 128; i++)
                if (raw[2 * i + 1] != 0u) { is64 = 0; break; }
            g_is64 = is64;
        }
    } else {
        g_degi[(b - 1) * 256 + threadIdx.x] = 0;
    }
}
__global__ void convert_edges_kernel(const void* __restrict__ rawp)
{
    int e = blockIdx.x * blockDim.x + threadIdx.x;
    if (e >= N_EDGES) return;
    int s, d;
    if (g_is64) {
        const long long* ei = (const long long*)rawp;
        s = (int)ei[e];
        d = (int)ei[N_EDGES + e];
    } else {
        const int* ei = (const int*)rawp;
        s = ei[e];
        d = ei[N_EDGES + e];
    }
    g_src[e] = s;
    g_dst[e] = d;
    atomicAdd(&g_degi[d], 1);
}

// ---------------------------------------------------------------------------
// fp32 -> (hi, lo) bf16 split, 8 elements per thread
// ---------------------------------------------------------------------------
__global__ void split_kernel(const float4* __restrict__ src,
                             uint4* __restrict__ hi, uint4* __restrict__ lo, int n8)
{
    int id = blockIdx.x * blockDim.x + threadIdx.x;
    if (id >= n8) return;
    float4 a = src[2 * id], b = src[2 * id + 1];
    float f[8] = { a.x, a.y, a.z, a.w, b.x, b.y, b.z, b.w };
    uint32_t H[4], L[4];
    #pragma unroll
    for (int i = 0; i < 4; i++) {
        __nv_bfloat16 h0 = __float2bfloat16(f[2 * i + 0]);
        __nv_bfloat16 h1 = __float2bfloat16(f[2 * i + 1]);
        __nv_bfloat16 l0 = __float2bfloat16(f[2 * i + 0] - __bfloat162float(h0));
        __nv_bfloat16 l1 = __float2bfloat16(f[2 * i + 1] - __bfloat162float(h1));
        __nv_bfloat162 hh(h0, h1), ll(l0, l1);
        H[i] = *(uint32_t*)&hh;
        L[i] = *(uint32_t*)&ll;
    }
    hi[id] = make_uint4(H[0], H[1], H[2], H[3]);
    lo[id] = make_uint4(L[0], L[1], L[2], L[3]);
}

// ---------------------------------------------------------------------------
// activations: fp32 [4096 x 256] (sum of 4 buffers) -> bf16 splits [256 x 4096]
// ---------------------------------------------------------------------------
__global__ void transpose_split_kernel(const float* __restrict__ s0,
                                       const float* __restrict__ s1,
                                       const float* __restrict__ s2,
                                       const float* __restrict__ s3,
                                       __nv_bfloat16* __restrict__ hi,
                                       __nv_bfloat16* __restrict__ lo)
{
    __shared__ float tile[32][33];
    int k0 = blockIdx.x * 32;
    int n0 = blockIdx.y * 32;
    int tx = threadIdx.x, ty = threadIdx.y;    // 32 x 8
    #pragma unroll
    for (int j = 0; j < 4; j++) {
        size_t o = (size_t)(k0 + ty + j * 8) * DIM + n0 + tx;
        float v = (s0[o] + s1[o]) + (s2[o] + s3[o]);
        tile[ty + j * 8][tx] = v;
    }
    __syncthreads();
    #pragma unroll
    for (int j = 0; j < 4; j++) {
        int n = ty + j * 8;
        float v = tile[tx][n];
        __nv_bfloat16 h = __float2bfloat16(v);
        __nv_bfloat16 l = __float2bfloat16(v - __bfloat162float(h));
        size_t o = (size_t)(n0 + n) * N_NODES + k0 + tx;
        hi[o] = h; lo[o] = l;
    }
}

// W [256 x 256] fp32 row-major -> W^T bf16 splits [256 x 256]
__global__ void wtranspose_split_kernel(const float* __restrict__ W,
                                        __nv_bfloat16* __restrict__ hi,
                                        __nv_bfloat16* __restrict__ lo)
{
    __shared__ float tile[32][33];
    int k0 = blockIdx.x * 32;
    int n0 = blockIdx.y * 32;
    int tx = threadIdx.x, ty = threadIdx.y;    // 32 x 8
    #pragma unroll
    for (int j = 0; j < 4; j++)
        tile[ty + j * 8][tx] = W[(size_t)(k0 + ty + j * 8) * DIM + n0 + tx];
    __syncthreads();
    #pragma unroll
    for (int j = 0; j < 4; j++) {
        int n = ty + j * 8;
        float v = tile[tx][n];
        __nv_bfloat16 h = __float2bfloat16(v);
        __nv_bfloat16 l = __float2bfloat16(v - __bfloat162float(h));
        size_t o = (size_t)(n0 + n) * DIM + k0 + tx;
        hi[o] = h; lo[o] = l;
    }
}

// ---------------------------------------------------------------------------
// mma.sync GEMM: CTA 128x128, BK=64, 128 threads / 4 warps, warp 64x64.
// OUT_MODE 0: fp32 to C0..C3 (per blockIdx.z)
//          1: fp16 (half2) to Ch
//          2: bf16 hi/lo split to Bh/Bl (+RELU)
//          4: atomicAdd(OutAdd, aH * v)  -- fused final combine
// ---------------------------------------------------------------------------
static constexpr int STAGES   = 3;
static constexpr int ROWB     = 144;
static constexpr int A_BYTES  = 128 * ROWB;
static constexpr int STAGE_B  = 2 * A_BYTES;
static constexpr int GEMM_SMEM = STAGES * STAGE_B;    // 110592

template <bool RELU, int OUT_MODE>
__global__ __launch_bounds__(128, 2) void gemm_mma_kernel(
    const __nv_bfloat16* __restrict__ Ahi, const __nv_bfloat16* __restrict__ Alo,
    const __nv_bfloat16* __restrict__ Bhi, const __nv_bfloat16* __restrict__ Blo,
    float* __restrict__ C0, float* __restrict__ C1,
    float* __restrict__ C2, float* __restrict__ C3,
    __half* __restrict__ Ch,
    __nv_bfloat16* __restrict__ Bh, __nv_bfloat16* __restrict__ Bl,
    float* __restrict__ OutAdd, const float* __restrict__ aHp,
    int strideA, int strideB, int strideC, int nit, int segShift)
{
    extern __shared__ char smem[];
    const uint32_t sbase = smem_u32(smem);
    const int t    = threadIdx.x;
    const int lane = t & 31;
    const int wid  = t >> 5;
    const int wm   = wid >> 1;
    const int wn   = wid & 1;
    const int m0   = blockIdx.y * 128;
    const int n0   = blockIdx.x * 128;
    const int cBeg = blockIdx.z * nit;
    const int segMask = (1 << segShift) - 1;

    const __nv_bfloat16* Aseg[3] = { Ahi, Ahi, Alo };
    const __nv_bfloat16* Bseg[3] = { Bhi, Blo, Bhi };

    const int rowBase = t >> 3;
    const int ch      = t & 7;
    uint32_t aOffG[8], bOffG[8], sOffA[8];
    #pragma unroll
    for (int i = 0; i < 8; i++) {
        int row = rowBase + 16 * i;
        aOffG[i] = (uint32_t)((m0 + row) * strideA + ch * 8);
        bOffG[i] = (uint32_t)((n0 + row) * strideB + ch * 8);
        sOffA[i] = (uint32_t)(row * ROWB + ch * 16);
    }

    const uint32_t aLd = (uint32_t)(wm * 64 + (lane & 15)) * ROWB + (lane >> 4) * 16;
    const uint32_t bLd = A_BYTES +
        (uint32_t)(wn * 64 + ((lane >> 4) & 1) * 8 + (lane & 7)) * ROWB + ((lane >> 3) & 1) * 16;

    float acc[4][8][4];
    #pragma unroll
    for (int f = 0; f < 4; f++)
        #pragma unroll
        for (int j = 0; j < 8; j++)
            #pragma unroll
            for (int e = 0; e < 4; e++) acc[f][j][e] = 0.f;

    auto load_stage = [&](int ci, int s) {
        if (ci < nit) {
            int c   = cBeg + ci;
            int seg = c >> segShift;
            int k0  = (c & segMask) << 6;
            const __nv_bfloat16* ap = Aseg[seg] + k0;
            const __nv_bfloat16* bp = Bseg[seg] + k0;
            uint32_t sb = sbase + s * STAGE_B;
            #pragma unroll
            for (int i = 0; i < 8; i++) cp_async16(sb + sOffA[i], ap + aOffG[i]);
            #pragma unroll
            for (int i = 0; i < 8; i++) cp_async16(sb + A_BYTES + sOffA[i], bp + bOffG[i]);
        }
        cp_commit();
    };

    load_stage(0, 0);
    load_stage(1, 1);

    for (int ci = 0; ci < nit; ci++) {
        cp_wait<STAGES - 2>();
        __syncthreads();
        load_stage(ci + STAGES - 1, (ci + STAGES - 1) % STAGES);

        uint32_t sb = sbase + (ci % STAGES) * STAGE_B;
        #pragma unroll
        for (int ks = 0; ks < 4; ks++) {
            uint32_t a[4][4], b[4][4];
            #pragma unroll
            for (int f = 0; f < 4; f++)
                ldsm_x4(a[f], sb + aLd + f * 16 * ROWB + ks * 32);
            #pragma unroll
            for (int g = 0; g < 4; g++)
                ldsm_x4(b[g], sb + bLd + g * 16 * ROWB + ks * 32);
            #pragma unroll
            for (int f = 0; f < 4; f++)
                #pragma unroll
                for (int g = 0; g < 4; g++) {
                    mma16816(acc[f][2 * g + 0], a[f], &b[g][0]);
                    mma16816(acc[f][2 * g + 1], a[f], &b[g][2]);
                }
        }
    }

    float* C = (blockIdx.z == 0) ? C0 : (blockIdx.z == 1) ? C1
             : (blockIdx.z == 2) ? C2 : C3;
    float aH = (OUT_MODE == 4) ? aHp[0] : 0.f;
    const int gid = lane >> 2;
    const int tig = lane & 3;
    #pragma unroll
    for (int f = 0; f < 4; f++) {
        int rbase = m0 + wm * 64 + f * 16 + gid;
        #pragma unroll
        for (int j = 0; j < 8; j++) {
            int col = n0 + wn * 64 + j * 8 + tig * 2;
            float2 v0 = { acc[f][j][0], acc[f][j][1] };
            float2 v1 = { acc[f][j][2], acc[f][j][3] };
            if (RELU) {
                v0.x = fmaxf(v0.x, 0.f); v0.y = fmaxf(v0.y, 0.f);
                v1.x = fmaxf(v1.x, 0.f); v1.y = fmaxf(v1.y, 0.f);
            }
            size_t o0 = (size_t)rbase * strideC + col;
            size_t o1 = (size_t)(rbase + 8) * strideC + col;
            if (OUT_MODE == 1) {
                __half2* Hp = (__half2*)Ch;
                Hp[o0 >> 1] = __floats2half2_rn(v0.x, v0.y);
                Hp[o1 >> 1] = __floats2half2_rn(v1.x, v1.y);
            } else if (OUT_MODE == 2) {
                __nv_bfloat16 h0 = __float2bfloat16(v0.x);
                __nv_bfloat16 h1 = __float2bfloat16(v0.y);
                __nv_bfloat16 l0 = __float2bfloat16(v0.x - __bfloat162float(h0));
                __nv_bfloat16 l1 = __float2bfloat16(v0.y - __bfloat162float(h1));
                *reinterpret_cast<__nv_bfloat162*>(Bh + o0) = __nv_bfloat162(h0, h1);
                *reinterpret_cast<__nv_bfloat162*>(Bl + o0) = __nv_bfloat162(l0, l1);
                __nv_bfloat16 h2 = __float2bfloat16(v1.x);
                __nv_bfloat16 h3 = __float2bfloat16(v1.y);
                __nv_bfloat16 l2 = __float2bfloat16(v1.x - __bfloat162float(h2));
                __nv_bfloat16 l3 = __float2bfloat16(v1.y - __bfloat162float(h3));
                *reinterpret_cast<__nv_bfloat162*>(Bh + o1) = __nv_bfloat162(h2, h3);
                *reinterpret_cast<__nv_bfloat162*>(Bl + o1) = __nv_bfloat162(l2, l3);
            } else if (OUT_MODE == 4) {
                atomicAdd(OutAdd + o0 + 0, aH * v0.x);
                atomicAdd(OutAdd + o0 + 1, aH * v0.y);
                atomicAdd(OutAdd + o1 + 0, aH * v1.x);
                atomicAdd(OutAdd + o1 + 1, aH * v1.y);
            } else {
                *reinterpret_cast<float2*>(C + o0) = v0;
                *reinterpret_cast<float2*>(C + o1) = v1;
            }
        }
    }
}

// ---------------------------------------------------------------------------
// CSR build
// ---------------------------------------------------------------------------
__global__ __launch_bounds__(1024) void csr_scan_kernel()
{
    __shared__ int part[1024];
    int t = threadIdx.x;
    int v0 = g_degi[4 * t + 0], v1 = g_degi[4 * t + 1];
    int v2 = g_degi[4 * t + 2], v3 = g_degi[4 * t + 3];
    int s1 = v0 + v1, s2 = s1 + v2, s3 = s2 + v3;
    part[t] = s3;
    __syncthreads();
    #pragma unroll
    for (int off = 1; off < 1024; off <<= 1) {
        int x = (t >= off) ? part[t - off] : 0;
        __syncthreads();
        part[t] += x;
        __syncthreads();
    }
    int base = t ? part[t - 1] : 0;
    g_rowoff[4 * t + 0] = base;
    g_rowoff[4 * t + 1] = base + v0;
    g_rowoff[4 * t + 2] = base + s1;
    g_rowoff[4 * t + 3] = base + s2;
    if (t == 1023) g_rowoff[4096] = base + s3;
    #pragma unroll
    for (int i = 0; i < 4; i++) {
        int n = 4 * t + i;
        int d = g_degi[n];
        g_dis[n] = rsqrtf((float)(d + 1));
        g_cursor[n] = 0;
    }
}
__global__ void csr_place_kernel()
{
    int e = blockIdx.x * blockDim.x + threadIdx.x;
    if (e >= N_EDGES) return;
    int dst = g_dst[e];
    int pos = g_rowoff[dst] + atomicAdd(&g_cursor[dst], 1);
    g_csr[pos] = g_src[e];
}

// ---------------------------------------------------------------------------
// Gather: Hl[dst] -> g_A (side stream)
// ---------------------------------------------------------------------------
__global__ __launch_bounds__(128) void gather_kernel()
{
    int dst = blockIdx.x;
    int t   = threadIdx.x;
    const __half2* XW = (const __half2*)g_XWh;
    float disD = g_dis[dst];
    float2 sv = __half22float2(XW[(size_t)dst * 128 + t]);
    float accx = sv.x * disD * disD;
    float accy = sv.y * disD * disD;
    int beg = g_rowoff[dst], end = g_rowoff[dst + 1];
    int j = beg;
    for (; j + 1 < end; j += 2) {
        int s0 = g_csr[j], s1 = g_csr[j + 1];
        float w0 = g_dis[s0] * disD, w1 = g_dis[s1] * disD;
        float2 v0 = __half22float2(XW[(size_t)s0 * 128 + t]);
        float2 v1 = __half22float2(XW[(size_t)s1 * 128 + t]);
        accx += v0.x * w0 + v1.x * w1;
        accy += v0.y * w0 + v1.y * w1;
    }
    if (j < end) {
        int s0 = g_csr[j];
        float w0 = g_dis[s0] * disD;
        float2 v0 = __half22float2(XW[(size_t)s0 * 128 + t]);
        accx += v0.x * w0;
        accy += v0.y * w0;
    }
    *reinterpret_cast<float2*>(g_A + (size_t)dst * DIM + 2 * t) = make_float2(accx, accy);
}

// out = aL*(Hl + b)  (GEMM3 epilogue atomically adds aH*Hh on top)
__global__ void init_out_kernel(float* __restrict__ out,
                                const float* __restrict__ b,
                                const float* __restrict__ aLp)
{
    int id = blockIdx.x * blockDim.x + threadIdx.x;
    if (id >= N_NODES * DIM / 4) return;
    float aL = aLp[0];
    int c4 = (id & (DIM / 4 - 1)) << 2;
    float4 hl = reinterpret_cast<const float4*>(g_A)[id];
    float4 bb = *reinterpret_cast<const float4*>(b + c4);
    float4 r;
    r.x = aL * (hl.x + bb.x);
    r.y = aL * (hl.y + bb.y);
    r.z = aL * (hl.z + bb.z);
    r.w = aL * (hl.w + bb.w);
    reinterpret_cast<float4*>(out)[id] = r;
}

// ---------------------------------------------------------------------------
extern "C" void kernel_launch(void* const* d_in, const int* in_sizes, int n_in,
                              void* d_out, int out_size)
{
    const float* x      = (const float*)d_in[0];
    const void*  ei_raw = d_in[1];
    const float* lap    = (const float*)d_in[2];
    const float* d_inv  = (const float*)d_in[3];
    const float* W_high = (const float*)d_in[4];
    const float* W_conv = (const float*)d_in[5];
    const float* b_conv = (const float*)d_in[6];
    const float* aL     = (const float*)d_in[7];
    const float* aH     = (const float*)d_in[8];
    float*       out    = (float*)d_out;

    float *pP0, *pP1, *pP2, *pP3;
    cudaGetSymbolAddress((void**)&pP0, g_P0);
    cudaGetSymbolAddress((void**)&pP1, g_P1);
    cudaGetSymbolAddress((void**)&pP2, g_P2);
    cudaGetSymbolAddress((void**)&pP3, g_P3);
    __half* pXWh;
    cudaGetSymbolAddress((void**)&pXWh, g_XWh);
    __nv_bfloat16 *pDh, *pDl, *pLh, *pLl, *pBh, *pBl, *pXh, *pXl, *pWh, *pWl, *pWh2, *pWl2;
    cudaGetSymbolAddress((void**)&pDh, g_dinv_hi);
    cudaGetSymbolAddress((void**)&pDl, g_dinv_lo);
    cudaGetSymbolAddress((void**)&pLh, g_lap_hi);
    cudaGetSymbolAddress((void**)&pLl, g_lap_lo);
    cudaGetSymbolAddress((void**)&pBh, g_Bhi);
    cudaGetSymbolAddress((void**)&pBl, g_Blo);
    cudaGetSymbolAddress((void**)&pXh, g_xhi);
    cudaGetSymbolAddress((void**)&pXl, g_xlo);
    cudaGetSymbolAddress((void**)&pWh, g_Wth);
    cudaGetSymbolAddress((void**)&pWl, g_Wtl);
    cudaGetSymbolAddress((void**)&pWh2, g_Wth2);
    cudaGetSymbolAddress((void**)&pWl2, g_Wtl2);

    cudaFuncSetAttribute(gemm_mma_kernel<false, 0>, cudaFuncAttributeMaxDynamicSharedMemorySize, GEMM_SMEM);
    cudaFuncSetAttribute(gemm_mma_kernel<false, 1>, cudaFuncAttributeMaxDynamicSharedMemorySize, GEMM_SMEM);
    cudaFuncSetAttribute(gemm_mma_kernel<true,  2>, cudaFuncAttributeMaxDynamicSharedMemorySize, GEMM_SMEM);
    cudaFuncSetAttribute(gemm_mma_kernel<false, 4>, cudaFuncAttributeMaxDynamicSharedMemorySize, GEMM_SMEM);

    // Streams + events
    cudaStream_t s1, s2;
    cudaStreamCreateWithFlags(&s1, cudaStreamNonBlocking);
    cudaStreamCreateWithFlags(&s2, cudaStreamNonBlocking);
    cudaEvent_t E0, Ex, Ed, El, Ei;
    cudaEventCreateWithFlags(&E0, cudaEventDisableTiming);
    cudaEventCreateWithFlags(&Ex, cudaEventDisableTiming);
    cudaEventCreateWithFlags(&Ed, cudaEventDisableTiming);
    cudaEventCreateWithFlags(&El, cudaEventDisableTiming);
    cudaEventCreateWithFlags(&Ei, cudaEventDisableTiming);

    dim3 gBig(DIM / 128, N_NODES / 128, 4);    // (2, 32, 4)
    dim3 gRT (N_NODES / 128, DIM / 128, 1);    // (32, 2) : C = R^T [256 x 4096]
    dim3 gSm (DIM / 128, N_NODES / 128, 1);    // (2, 32) : XW_conv [4096 x 256]
    dim3 gTr(N_NODES / 32, DIM / 32);
    dim3 bTr(32, 8);
    dim3 gWt(DIM / 32, DIM / 32);
    const int NIT_BIG = (3 * N_NODES / 64) / 4;   // 48 per z
    const int NIT_SM  = 3 * DIM / 64;             // 12
    const int SEG_BIG = 6;
    const int SEG_SM  = 2;
    int nbig8 = N_NODES * N_NODES / 8;
    int nx8   = N_NODES * DIM / 8;
    int nvec  = N_NODES * DIM / 4;

    // ---- fork ----
    cudaEventRecord(E0, 0);
    cudaStreamWaitEvent(s1, E0, 0);
    cudaStreamWaitEvent(s2, E0, 0);

    // s1: big matrix splits
    split_kernel<<<nbig8 / 256, 256, 0, s1>>>((const float4*)d_inv, (uint4*)pDh, (uint4*)pDl, nbig8);
    cudaEventRecord(Ed, s1);
    split_kernel<<<nbig8 / 256, 256, 0, s1>>>((const float4*)lap, (uint4*)pLh, (uint4*)pLl, nbig8);
    cudaEventRecord(El, s1);

    // s2: edge conversion + CSR + W_conv transpose; XW_conv GEMM; gather; init_out
    detect_init_kernel  <<<17, 256, 0, s2>>>((const unsigned int*)ei_raw);
    convert_edges_kernel<<<N_EDGES / 256, 256, 0, s2>>>(ei_raw);
    csr_scan_kernel     <<<1, 1024, 0, s2>>>();
    csr_place_kernel    <<<N_EDGES / 256, 256, 0, s2>>>();
    wtranspose_split_kernel<<<gWt, bTr, 0, s2>>>(W_conv, pWh2, pWl2);

    // s0: prologue — x splits first (gates both downstream GEMMs), then W_high^T
    split_kernel<<<nx8 / 256, 256>>>((const float4*)x, (uint4*)pXh, (uint4*)pXl, nx8);
    cudaEventRecord(Ex, 0);
    wtranspose_split_kernel<<<gWt, bTr>>>(W_high, pWh, pWl);

    // s2 continues: XW_conv = x @ W_conv (fp16 out), gather, init_out
    cudaStreamWaitEvent(s2, Ex, 0);
    gemm_mma_kernel<false, 1><<<gSm, 128, GEMM_SMEM, s2>>>(pXh, pXl, pWh2, pWl2,
        nullptr, nullptr, nullptr, nullptr, pXWh, nullptr, nullptr, nullptr, nullptr,
        DIM, DIM, DIM, NIT_SM, SEG_SM);
    gather_kernel<<<N_NODES, 128, 0, s2>>>();
    init_out_kernel<<<(nvec + 255) / 256, 256, 0, s2>>>(out, b_conv, aL);
    cudaEventRecord(Ei, s2);

    // s0: R^T = relu(W_high^T @ x^T) with fused bf16-split epilogue -> Bhi/Blo
    gemm_mma_kernel<true, 2><<<gRT, 128, GEMM_SMEM>>>(pWh, pWl, pXh, pXl,
        nullptr, nullptr, nullptr, nullptr, nullptr, pBh, pBl, nullptr, nullptr,
        DIM, DIM, N_NODES, NIT_SM, SEG_SM);
    // T1 = d_inv @ R
    cudaStreamWaitEvent(0, Ed, 0);
    gemm_mma_kernel<false, 0><<<gBig, 128, GEMM_SMEM>>>(pDh, pDl, pBh, pBl,
        pP0, pP1, pP2, pP3, nullptr, nullptr, nullptr, nullptr, nullptr,
        N_NODES, N_NODES, DIM, NIT_BIG, SEG_BIG);
    // T2 = lap @ T1
    transpose_split_kernel<<<gTr, bTr>>>(pP0, pP1, pP2, pP3, pBh, pBl);
    cudaStreamWaitEvent(0, El, 0);
    gemm_mma_kernel<false, 0><<<gBig, 128, GEMM_SMEM>>>(pLh, pLl, pBh, pBl,
        pP0, pP1, pP2, pP3, nullptr, nullptr, nullptr, nullptr, nullptr,
        N_NODES, N_NODES, DIM, NIT_BIG, SEG_BIG);
    // Hh = d_inv @ T2, epilogue fuses: out += aH * Hh  (out pre-set to aL*(Hl+b))
    transpose_split_kernel<<<gTr, bTr>>>(pP0, pP1, pP2, pP3, pBh, pBl);
    cudaStreamWaitEvent(0, Ei, 0);
    gemm_mma_kernel<false, 4><<<gBig, 128, GEMM_SMEM>>>(pDh, pDl, pBh, pBl,
        nullptr, nullptr, nullptr, nullptr, nullptr, nullptr, nullptr, out, aH,
        N_NODES, N_NODES, DIM, NIT_BIG, SEG_BIG);

    cudaEventDestroy(E0); cudaEventDestroy(Ex); cudaEventDestroy(Ed);
    cudaEventDestroy(El); cudaEventDestroy(Ei);
    cudaStreamDestroy(s1); cudaStreamDestroy(s2);
}

// round 15
// speedup vs baseline: 3.4245x; 1.2679x over previous
#include <cuda_runtime.h>
#include <cuda_bf16.h>
#include <cuda_fp16.h>
#include <cstdint>

// FBGCN layer:
//   Hh = d_inv @ (lap @ (d_inv @ relu(x @ W_high)))
//     big GEMMs: fp16 2-digit split A x single-fp16 B (K_eff = 8192)
//   Hl = GCNConv(x, edge_index, W_conv, b_conv)  -- CSR gather (fp16 features)
//   out = aL*Hl + aH*Hh (fused into GEMM3 atomic epilogue)

static constexpr int N_NODES = 4096;
static constexpr int DIM     = 256;
static constexpr int N_EDGES = 131072;

// fp32 scratch
__device__ __align__(16) float g_A[N_NODES * DIM];    // Hl
__device__ __align__(16) float g_P0[N_NODES * DIM];   // split-K partials
__device__ __align__(16) float g_P1[N_NODES * DIM];
__device__ __align__(16) float g_P2[N_NODES * DIM];
__device__ __align__(16) float g_P3[N_NODES * DIM];
__device__ __align__(16) __half g_XWh[N_NODES * DIM]; // XW_conv fp16 (gather)
__device__ float g_dis[N_NODES];
__device__ int   g_src[N_EDGES];
__device__ int   g_dst[N_EDGES];
__device__ int   g_is64;
// CSR
__device__ int   g_degi[N_NODES];
__device__ int   g_rowoff[N_NODES + 1];
__device__ int   g_cursor[N_NODES];
__device__ int   g_csr[N_EDGES];

// fp16 split buffers (big matrices) + single-plane activation
__device__ __align__(128) __half g_dinv_hi[(size_t)N_NODES * N_NODES];
__device__ __align__(128) __half g_dinv_lo[(size_t)N_NODES * N_NODES];
__device__ __align__(128) __half g_lap_hi [(size_t)N_NODES * N_NODES];
__device__ __align__(128) __half g_lap_lo [(size_t)N_NODES * N_NODES];
__device__ __align__(128) __half g_Bf[DIM * N_NODES];       // act^T [256 x 4096] fp16

// bf16 buffers for the two small GEMMs
__device__ __align__(128) __nv_bfloat16 g_xhi[N_NODES * DIM];
__device__ __align__(128) __nv_bfloat16 g_xlo[N_NODES * DIM];
__device__ __align__(128) __nv_bfloat16 g_Wth[DIM * DIM];    // W_high^T splits
__device__ __align__(128) __nv_bfloat16 g_Wtl[DIM * DIM];
__device__ __align__(128) __nv_bfloat16 g_Wth2[DIM * DIM];   // W_conv^T splits
__device__ __align__(128) __nv_bfloat16 g_Wtl2[DIM * DIM];

// ---------------------------------------------------------------------------
// PTX helpers
// ---------------------------------------------------------------------------
__device__ __forceinline__ uint32_t smem_u32(const void* p) {
    uint32_t a;
    asm("{ .reg .u64 t; cvta.to.shared.u64 t, %1; cvt.u32.u64 %0, t; }" : "=r"(a) : "l"(p));
    return a;
}
__device__ __forceinline__ void cp_async16(uint32_t dst, const void* src) {
    asm volatile("cp.async.cg.shared.global [%0], [%1], 16;" :: "r"(dst), "l"(src) : "memory");
}
__device__ __forceinline__ void cp_commit() { asm volatile("cp.async.commit_group;" ::: "memory"); }
template <int N>
__device__ __forceinline__ void cp_wait() { asm volatile("cp.async.wait_group %0;" :: "n"(N) : "memory"); }

__device__ __forceinline__ void ldsm_x4(uint32_t* r, uint32_t addr) {
    asm volatile("ldmatrix.sync.aligned.m8n8.x4.shared.b16 {%0,%1,%2,%3}, [%4];"
        : "=r"(r[0]), "=r"(r[1]), "=r"(r[2]), "=r"(r[3]) : "r"(addr));
}
__device__ __forceinline__ void mma_bf16(float* c, const uint32_t* a, const uint32_t* b) {
    asm volatile("mma.sync.aligned.m16n8k16.row.col.f32.bf16.bf16.f32 "
        "{%0,%1,%2,%3}, {%4,%5,%6,%7}, {%8,%9}, {%0,%1,%2,%3};"
        : "+f"(c[0]), "+f"(c[1]), "+f"(c[2]), "+f"(c[3])
        : "r"(a[0]), "r"(a[1]), "r"(a[2]), "r"(a[3]), "r"(b[0]), "r"(b[1]));
}
__device__ __forceinline__ void mma_f16(float* c, const uint32_t* a, const uint32_t* b) {
    asm volatile("mma.sync.aligned.m16n8k16.row.col.f32.f16.f16.f32 "
        "{%0,%1,%2,%3}, {%4,%5,%6,%7}, {%8,%9}, {%0,%1,%2,%3};"
        : "+f"(c[0]), "+f"(c[1]), "+f"(c[2]), "+f"(c[3])
        : "r"(a[0]), "r"(a[1]), "r"(a[2]), "r"(a[3]), "r"(b[0]), "r"(b[1]));
}

// ---------------------------------------------------------------------------
// detect dtype + zero degree counters; edge convert + degree count
// ---------------------------------------------------------------------------
__global__ void detect_init_kernel(const unsigned int* __restrict__ raw)
{
    int b = blockIdx.x;
    if (b == 0) {
        if (threadIdx.x == 0) {
            int is64 = 1;
            #pragma unroll 1
            for (int i = 0; i < 128; i++)
                if (raw[2 * i + 1] != 0u) { is64 = 0; break; }
            g_is64 = is64;
        }
    } else {
        g_degi[(b - 1) * 256 + threadIdx.x] = 0;
    }
}
__global__ void convert_edges_kernel(const void* __restrict__ rawp)
{
    int e = blockIdx.x * blockDim.x + threadIdx.x;
    if (e >= N_EDGES) return;
    int s, d;
    if (g_is64) {
        const long long* ei = (const long long*)rawp;
        s = (int)ei[e];
        d = (int)ei[N_EDGES + e];
    } else {
        const int* ei = (const int*)rawp;
        s = ei[e];
        d = ei[N_EDGES + e];
    }
    g_src[e] = s;
    g_dst[e] = d;
    atomicAdd(&g_degi[d], 1);
}

// ---------------------------------------------------------------------------
// fp32 -> (hi, lo) fp16 split (big matrices), 8 elems/thread
// ---------------------------------------------------------------------------
__global__ void splith_kernel(const float4* __restrict__ src,
                              uint4* __restrict__ hi, uint4* __restrict__ lo, int n8)
{
    int id = blockIdx.x * blockDim.x + threadIdx.x;
    if (id >= n8) return;
    float4 a = src[2 * id], b = src[2 * id + 1];
    float f[8] = { a.x, a.y, a.z, a.w, b.x, b.y, b.z, b.w };
    uint32_t H[4], L[4];
    #pragma unroll
    for (int i = 0; i < 4; i++) {
        __half h0 = __float2half_rn(f[2 * i + 0]);
        __half h1 = __float2half_rn(f[2 * i + 1]);
        __half l0 = __float2half_rn(f[2 * i + 0] - __half2float(h0));
        __half l1 = __float2half_rn(f[2 * i + 1] - __half2float(h1));
        __half2 hh = __halves2half2(h0, h1), ll = __halves2half2(l0, l1);
        H[i] = *(uint32_t*)&hh;
        L[i] = *(uint32_t*)&ll;
    }
    hi[id] = make_uint4(H[0], H[1], H[2], H[3]);
    lo[id] = make_uint4(L[0], L[1], L[2], L[3]);
}

// fp32 -> bf16 hi/lo split (x)
__global__ void split_kernel(const float4* __restrict__ src,
                             uint4* __restrict__ hi, uint4* __restrict__ lo, int n8)
{
    int id = blockIdx.x * blockDim.x + threadIdx.x;
    if (id >= n8) return;
    float4 a = src[2 * id], b = src[2 * id + 1];
    float f[8] = { a.x, a.y, a.z, a.w, b.x, b.y, b.z, b.w };
    uint32_t H[4], L[4];
    #pragma unroll
    for (int i = 0; i < 4; i++) {
        __nv_bfloat16 h0 = __float2bfloat16(f[2 * i + 0]);
        __nv_bfloat16 h1 = __float2bfloat16(f[2 * i + 1]);
        __nv_bfloat16 l0 = __float2bfloat16(f[2 * i + 0] - __bfloat162float(h0));
        __nv_bfloat16 l1 = __float2bfloat16(f[2 * i + 1] - __bfloat162float(h1));
        __nv_bfloat162 hh(h0, h1), ll(l0, l1);
        H[i] = *(uint32_t*)&hh;
        L[i] = *(uint32_t*)&ll;
    }
    hi[id] = make_uint4(H[0], H[1], H[2], H[3]);
    lo[id] = make_uint4(L[0], L[1], L[2], L[3]);
}

// ---------------------------------------------------------------------------
// sum 4 partials [4096 x 256] -> fp16 transposed [256 x 4096], scaled
// ---------------------------------------------------------------------------
__global__ void transpose_sum4h_kernel(const float* __restrict__ s0,
                                       const float* __restrict__ s1,
                                       const float* __restrict__ s2,
                                       const float* __restrict__ s3,
                                       __half* __restrict__ dst, float wScale)
{
    __shared__ float tile[32][33];
    int k0 = blockIdx.x * 32;
    int n0 = blockIdx.y * 32;
    int tx = threadIdx.x, ty = threadIdx.y;    // 32 x 8
    #pragma unroll
    for (int j = 0; j < 4; j++) {
        size_t o = (size_t)(k0 + ty + j * 8) * DIM + n0 + tx;
        tile[ty + j * 8][tx] = (s0[o] + s1[o]) + (s2[o] + s3[o]);
    }
    __syncthreads();
    #pragma unroll
    for (int j = 0; j < 4; j++) {
        int n = ty + j * 8;
        dst[(size_t)(n0 + n) * N_NODES + k0 + tx] = __float2half_rn(tile[tx][n] * wScale);
    }
}

// W [256 x 256] fp32 row-major -> W^T bf16 splits [256 x 256]
__global__ void wtranspose_split_kernel(const float* __restrict__ W,
                                        __nv_bfloat16* __restrict__ hi,
                                        __nv_bfloat16* __restrict__ lo)
{
    __shared__ float tile[32][33];
    int k0 = blockIdx.x * 32;
    int n0 = blockIdx.y * 32;
    int tx = threadIdx.x, ty = threadIdx.y;
    #pragma unroll
    for (int j = 0; j < 4; j++)
        tile[ty + j * 8][tx] = W[(size_t)(k0 + ty + j * 8) * DIM + n0 + tx];
    __syncthreads();
    #pragma unroll
    for (int j = 0; j < 4; j++) {
        int n = ty + j * 8;
        float v = tile[tx][n];
        __nv_bfloat16 h = __float2bfloat16(v);
        __nv_bfloat16 l = __float2bfloat16(v - __bfloat162float(h));
        size_t o = (size_t)(n0 + n) * DIM + k0 + tx;
        hi[o] = h; lo[o] = l;
    }
}

// ---------------------------------------------------------------------------
// Shared GEMM geometry
// ---------------------------------------------------------------------------
static constexpr int STAGES   = 3;
static constexpr int ROWB     = 144;
static constexpr int A_BYTES  = 128 * ROWB;
static constexpr int STAGE_B  = 2 * A_BYTES;
static constexpr int GEMM_SMEM = STAGES * STAGE_B;    // 110592

// ---------------------------------------------------------------------------
// bf16 3-term GEMM (small GEMMs): OUT_MODE 1 = fp16 out (stride strideC)
// ---------------------------------------------------------------------------
template <bool RELU>
__global__ __launch_bounds__(128, 2) void gemm_bf16_kernel(
    const __nv_bfloat16* __restrict__ Ahi, const __nv_bfloat16* __restrict__ Alo,
    const __nv_bfloat16* __restrict__ Bhi, const __nv_bfloat16* __restrict__ Blo,
    __half* __restrict__ Ch,
    int strideA, int strideB, int strideC, int nit, int segShift)
{
    extern __shared__ char smem[];
    const uint32_t sbase = smem_u32(smem);
    const int t    = threadIdx.x;
    const int lane = t & 31;
    const int wid  = t >> 5;
    const int wm   = wid >> 1;
    const int wn   = wid & 1;
    const int m0   = blockIdx.y * 128;
    const int n0   = blockIdx.x * 128;
    const int segMask = (1 << segShift) - 1;

    const __nv_bfloat16* Aseg[3] = { Ahi, Ahi, Alo };
    const __nv_bfloat16* Bseg[3] = { Bhi, Blo, Bhi };

    const int rowBase = t >> 3;
    const int ch      = t & 7;
    uint32_t aOffG[8], bOffG[8], sOffA[8];
    #pragma unroll
    for (int i = 0; i < 8; i++) {
        int row = rowBase + 16 * i;
        aOffG[i] = (uint32_t)((m0 + row) * strideA + ch * 8);
        bOffG[i] = (uint32_t)((n0 + row) * strideB + ch * 8);
        sOffA[i] = (uint32_t)(row * ROWB + ch * 16);
    }
    const uint32_t aLd = (uint32_t)(wm * 64 + (lane & 15)) * ROWB + (lane >> 4) * 16;
    const uint32_t bLd = A_BYTES +
        (uint32_t)(wn * 64 + ((lane >> 4) & 1) * 8 + (lane & 7)) * ROWB + ((lane >> 3) & 1) * 16;

    float acc[4][8][4];
    #pragma unroll
    for (int f = 0; f < 4; f++)
        #pragma unroll
        for (int j = 0; j < 8; j++)
            #pragma unroll
            for (int e = 0; e < 4; e++) acc[f][j][e] = 0.f;

    auto load_stage = [&](int ci, int s) {
        if (ci < nit) {
            int seg = ci >> segShift;
            int k0  = (ci & segMask) << 6;
            const __nv_bfloat16* ap = Aseg[seg] + k0;
            const __nv_bfloat16* bp = Bseg[seg] + k0;
            uint32_t sb = sbase + s * STAGE_B;
            #pragma unroll
            for (int i = 0; i < 8; i++) cp_async16(sb + sOffA[i], ap + aOffG[i]);
            #pragma unroll
            for (int i = 0; i < 8; i++) cp_async16(sb + A_BYTES + sOffA[i], bp + bOffG[i]);
        }
        cp_commit();
    };

    load_stage(0, 0);
    load_stage(1, 1);

    for (int ci = 0; ci < nit; ci++) {
        cp_wait<STAGES - 2>();
        __syncthreads();
        load_stage(ci + STAGES - 1, (ci + STAGES - 1) % STAGES);

        uint32_t sb = sbase + (ci % STAGES) * STAGE_B;
        #pragma unroll
        for (int ks = 0; ks < 4; ks++) {
            uint32_t a[4][4], b[4][4];
            #pragma unroll
            for (int f = 0; f < 4; f++)
                ldsm_x4(a[f], sb + aLd + f * 16 * ROWB + ks * 32);
            #pragma unroll
            for (int g = 0; g < 4; g++)
                ldsm_x4(b[g], sb + bLd + g * 16 * ROWB + ks * 32);
            #pragma unroll
            for (int f = 0; f < 4; f++)
                #pragma unroll
                for (int g = 0; g < 4; g++) {
                    mma_bf16(acc[f][2 * g + 0], a[f], &b[g][0]);
                    mma_bf16(acc[f][2 * g + 1], a[f], &b[g][2]);
                }
        }
    }

    const int gid = lane >> 2;
    const int tig = lane & 3;
    #pragma unroll
    for (int f = 0; f < 4; f++) {
        int rbase = m0 + wm * 64 + f * 16 + gid;
        #pragma unroll
        for (int j = 0; j < 8; j++) {
            int col = n0 + wn * 64 + j * 8 + tig * 2;
            float2 v0 = { acc[f][j][0], acc[f][j][1] };
            float2 v1 = { acc[f][j][2], acc[f][j][3] };
            if (RELU) {
                v0.x = fmaxf(v0.x, 0.f); v0.y = fmaxf(v0.y, 0.f);
                v1.x = fmaxf(v1.x, 0.f); v1.y = fmaxf(v1.y, 0.f);
            }
            size_t o0 = (size_t)rbase * strideC + col;
            size_t o1 = (size_t)(rbase + 8) * strideC + col;
            __half2* Hp = (__half2*)Ch;
            Hp[o0 >> 1] = __floats2half2_rn(v0.x, v0.y);
            Hp[o1 >> 1] = __floats2half2_rn(v1.x, v1.y);
        }
    }
}

// ---------------------------------------------------------------------------
// fp16 2-term GEMM (big GEMMs): A = Ah+Al (fp16 split), B single fp16.
// K_eff = 2 x 4096 = 8192; split-K z=4, 32 iters each, segShift=6.
// OUT_MODE 0: fp32 x outScale to C0..C3.  OUT_MODE 4: atomicAdd(Out, aH*outScale*v).
// ---------------------------------------------------------------------------
template <int OUT_MODE>
__global__ __launch_bounds__(128, 2) void gemm_f16_kernel(
    const __half* __restrict__ Ah, const __half* __restrict__ Al,
    const __half* __restrict__ B,
    float* __restrict__ C0, float* __restrict__ C1,
    float* __restrict__ C2, float* __restrict__ C3,
    float* __restrict__ OutAdd, const float* __restrict__ aHp, float outScale)
{
    extern __shared__ char smem[];
    const uint32_t sbase = smem_u32(smem);
    const int t    = threadIdx.x;
    const int lane = t & 31;
    const int wid  = t >> 5;
    const int wm   = wid >> 1;
    const int wn   = wid & 1;
    const int m0   = blockIdx.y * 128;
    const int n0   = blockIdx.x * 128;
    const int cBeg = blockIdx.z * 32;          // 32 iters per z, 128 total

    const __half* Aseg[2] = { Ah, Al };

    const int rowBase = t >> 3;
    const int ch      = t & 7;
    uint32_t aOffG[8], bOffG[8], sOffA[8];
    #pragma unroll
    for (int i = 0; i < 8; i++) {
        int row = rowBase + 16 * i;
        aOffG[i] = (uint32_t)((m0 + row) * N_NODES + ch * 8);
        bOffG[i] = (uint32_t)((n0 + row) * N_NODES + ch * 8);
        sOffA[i] = (uint32_t)(row * ROWB + ch * 16);
    }
    const uint32_t aLd = (uint32_t)(wm * 64 + (lane & 15)) * ROWB + (lane >> 4) * 16;
    const uint32_t bLd = A_BYTES +
        (uint32_t)(wn * 64 + ((lane >> 4) & 1) * 8 + (lane & 7)) * ROWB + ((lane >> 3) & 1) * 16;

    float acc[4][8][4];
    #pragma unroll
    for (int f = 0; f < 4; f++)
        #pragma unroll
        for (int j = 0; j < 8; j++)
            #pragma unroll
            for (int e = 0; e < 4; e++) acc[f][j][e] = 0.f;

    auto load_stage = [&](int ci, int s) {
        if (ci < 32) {
            int c   = cBeg + ci;
            int seg = c >> 6;                  // 64 iters per segment
            int k0  = (c & 63) << 6;
            const __half* ap = Aseg[seg] + k0;
            const __half* bp = B + k0;
            uint32_t sb = sbase + s * STAGE_B;
            #pragma unroll
            for (int i = 0; i < 8; i++) cp_async16(sb + sOffA[i], ap + aOffG[i]);
            #pragma unroll
            for (int i = 0; i < 8; i++) cp_async16(sb + A_BYTES + sOffA[i], bp + bOffG[i]);
        }
        cp_commit();
    };

    load_stage(0, 0);
    load_stage(1, 1);

    for (int ci = 0; ci < 32; ci++) {
        cp_wait<STAGES - 2>();
        __syncthreads();
        load_stage(ci + STAGES - 1, (ci + STAGES - 1) % STAGES);

        uint32_t sb = sbase + (ci % STAGES) * STAGE_B;
        #pragma unroll
        for (int ks = 0; ks < 4; ks++) {
            uint32_t a[4][4], b[4][4];
            #pragma unroll
            for (int f = 0; f < 4; f++)
                ldsm_x4(a[f], sb + aLd + f * 16 * ROWB + ks * 32);
            #pragma unroll
            for (int g = 0; g < 4; g++)
                ldsm_x4(b[g], sb + bLd + g * 16 * ROWB + ks * 32);
            #pragma unroll
            for (int f = 0; f < 4; f++)
                #pragma unroll
                for (int g = 0; g < 4; g++) {
                    mma_f16(acc[f][2 * g + 0], a[f], &b[g][0]);
                    mma_f16(acc[f][2 * g + 1], a[f], &b[g][2]);
                }
        }
    }

    float* C = (blockIdx.z == 0) ? C0 : (blockIdx.z == 1) ? C1
             : (blockIdx.z == 2) ? C2 : C3;
    float sc = (OUT_MODE == 4) ? aHp[0] * outScale : outScale;
    const int gid = lane >> 2;
    const int tig = lane & 3;
    #pragma unroll
    for (int f = 0; f < 4; f++) {
        int rbase = m0 + wm * 64 + f * 16 + gid;
        #pragma unroll
        for (int j = 0; j < 8; j++) {
            int col = n0 + wn * 64 + j * 8 + tig * 2;
            float2 v0 = { acc[f][j][0] * sc, acc[f][j][1] * sc };
            float2 v1 = { acc[f][j][2] * sc, acc[f][j][3] * sc };
            size_t o0 = (size_t)rbase * DIM + col;
            size_t o1 = (size_t)(rbase + 8) * DIM + col;
            if (OUT_MODE == 4) {
                atomicAdd(OutAdd + o0 + 0, v0.x);
                atomicAdd(OutAdd + o0 + 1, v0.y);
                atomicAdd(OutAdd + o1 + 0, v1.x);
                atomicAdd(OutAdd + o1 + 1, v1.y);
            } else {
                *reinterpret_cast<float2*>(C + o0) = v0;
                *reinterpret_cast<float2*>(C + o1) = v1;
            }
        }
    }
}

// ---------------------------------------------------------------------------
// CSR build
// ---------------------------------------------------------------------------
__global__ __launch_bounds__(1024) void csr_scan_kernel()
{
    __shared__ int part[1024];
    int t = threadIdx.x;
    int v0 = g_degi[4 * t + 0], v1 = g_degi[4 * t + 1];
    int v2 = g_degi[4 * t + 2], v3 = g_degi[4 * t + 3];
    int s1 = v0 + v1, s2 = s1 + v2, s3 = s2 + v3;
    part[t] = s3;
    __syncthreads();
    #pragma unroll
    for (int off = 1; off < 1024; off <<= 1) {
        int x = (t >= off) ? part[t - off] : 0;
        __syncthreads();
        part[t] += x;
        __syncthreads();
    }
    int base = t ? part[t - 1] : 0;
    g_rowoff[4 * t + 0] = base;
    g_rowoff[4 * t + 1] = base + v0;
    g_rowoff[4 * t + 2] = base + s1;
    g_rowoff[4 * t + 3] = base + s2;
    if (t == 1023) g_rowoff[4096] = base + s3;
    #pragma unroll
    for (int i = 0; i < 4; i++) {
        int n = 4 * t + i;
        int d = g_degi[n];
        g_dis[n] = rsqrtf((float)(d + 1));
        g_cursor[n] = 0;
    }
}
__global__ void csr_place_kernel()
{
    int e = blockIdx.x * blockDim.x + threadIdx.x;
    if (e >= N_EDGES) return;
    int dst = g_dst[e];
    int pos = g_rowoff[dst] + atomicAdd(&g_cursor[dst], 1);
    g_csr[pos] = g_src[e];
}

// ---------------------------------------------------------------------------
// Gather: Hl[dst] -> g_A (side stream)
// ---------------------------------------------------------------------------
__global__ __launch_bounds__(128) void gather_kernel()
{
    int dst = blockIdx.x;
    int t   = threadIdx.x;
    const __half2* XW = (const __half2*)g_XWh;
    float disD = g_dis[dst];
    float2 sv = __half22float2(XW[(size_t)dst * 128 + t]);
    float accx = sv.x * disD * disD;
    float accy = sv.y * disD * disD;
    int beg = g_rowoff[dst], end = g_rowoff[dst + 1];
    int j = beg;
    for (; j + 1 < end; j += 2) {
        int s0 = g_csr[j], s1 = g_csr[j + 1];
        float w0 = g_dis[s0] * disD, w1 = g_dis[s1] * disD;
        float2 v0 = __half22float2(XW[(size_t)s0 * 128 + t]);
        float2 v1 = __half22float2(XW[(size_t)s1 * 128 + t]);
        accx += v0.x * w0 + v1.x * w1;
        accy += v0.y * w0 + v1.y * w1;
    }
    if (j < end) {
        int s0 = g_csr[j];
        float w0 = g_dis[s0] * disD;
        float2 v0 = __half22float2(XW[(size_t)s0 * 128 + t]);
        accx += v0.x * w0;
        accy += v0.y * w0;
    }
    *reinterpret_cast<float2*>(g_A + (size_t)dst * DIM + 2 * t) = make_float2(accx, accy);
}

// out = aL*(Hl + b)  (GEMM3 epilogue atomically adds aH*Hh on top)
__global__ void init_out_kernel(float* __restrict__ out,
                                const float* __restrict__ b,
                                const float* __restrict__ aLp)
{
    int id = blockIdx.x * blockDim.x + threadIdx.x;
    if (id >= N_NODES * DIM / 4) return;
    float aL = aLp[0];
    int c4 = (id & (DIM / 4 - 1)) << 2;
    float4 hl = reinterpret_cast<const float4*>(g_A)[id];
    float4 bb = *reinterpret_cast<const float4*>(b + c4);
    float4 r;
    r.x = aL * (hl.x + bb.x);
    r.y = aL * (hl.y + bb.y);
    r.z = aL * (hl.z + bb.z);
    r.w = aL * (hl.w + bb.w);
    reinterpret_cast<float4*>(out)[id] = r;
}

// ---------------------------------------------------------------------------
extern "C" void kernel_launch(void* const* d_in, const int* in_sizes, int n_in,
                              void* d_out, int out_size)
{
    const float* x      = (const float*)d_in[0];
    const void*  ei_raw = d_in[1];
    const float* lap    = (const float*)d_in[2];
    const float* d_inv  = (const float*)d_in[3];
    const float* W_high = (const float*)d_in[4];
    const float* W_conv = (const float*)d_in[5];
    const float* b_conv = (const float*)d_in[6];
    const float* aL     = (const float*)d_in[7];
    const float* aH     = (const float*)d_in[8];
    float*       out    = (float*)d_out;

    float *pP0, *pP1, *pP2, *pP3;
    cudaGetSymbolAddress((void**)&pP0, g_P0);
    cudaGetSymbolAddress((void**)&pP1, g_P1);
    cudaGetSymbolAddress((void**)&pP2, g_P2);
    cudaGetSymbolAddress((void**)&pP3, g_P3);
    __half *pXWh, *pDh, *pDl, *pLh, *pLl, *pBf;
    cudaGetSymbolAddress((void**)&pXWh, g_XWh);
    cudaGetSymbolAddress((void**)&pDh, g_dinv_hi);
    cudaGetSymbolAddress((void**)&pDl, g_dinv_lo);
    cudaGetSymbolAddress((void**)&pLh, g_lap_hi);
    cudaGetSymbolAddress((void**)&pLl, g_lap_lo);
    cudaGetSymbolAddress((void**)&pBf, g_Bf);
    __nv_bfloat16 *pXh, *pXl, *pWh, *pWl, *pWh2, *pWl2;
    cudaGetSymbolAddress((void**)&pXh, g_xhi);
    cudaGetSymbolAddress((void**)&pXl, g_xlo);
    cudaGetSymbolAddress((void**)&pWh, g_Wth);
    cudaGetSymbolAddress((void**)&pWl, g_Wtl);
    cudaGetSymbolAddress((void**)&pWh2, g_Wth2);
    cudaGetSymbolAddress((void**)&pWl2, g_Wtl2);

    cudaFuncSetAttribute(gemm_bf16_kernel<false>, cudaFuncAttributeMaxDynamicSharedMemorySize, GEMM_SMEM);
    cudaFuncSetAttribute(gemm_bf16_kernel<true >, cudaFuncAttributeMaxDynamicSharedMemorySize, GEMM_SMEM);
    cudaFuncSetAttribute(gemm_f16_kernel<0>, cudaFuncAttributeMaxDynamicSharedMemorySize, GEMM_SMEM);
    cudaFuncSetAttribute(gemm_f16_kernel<4>, cudaFuncAttributeMaxDynamicSharedMemorySize, GEMM_SMEM);

    cudaStream_t s1, s2;
    cudaStreamCreateWithFlags(&s1, cudaStreamNonBlocking);
    cudaStreamCreateWithFlags(&s2, cudaStreamNonBlocking);
    cudaEvent_t E0, Ex, Ed, El, Ei;
    cudaEventCreateWithFlags(&E0, cudaEventDisableTiming);
    cudaEventCreateWithFlags(&Ex, cudaEventDisableTiming);
    cudaEventCreateWithFlags(&Ed, cudaEventDisableTiming);
    cudaEventCreateWithFlags(&El, cudaEventDisableTiming);
    cudaEventCreateWithFlags(&Ei, cudaEventDisableTiming);

    dim3 gBig(DIM / 128, N_NODES / 128, 4);    // (2, 32, 4)
    dim3 gRT (N_NODES / 128, DIM / 128, 1);    // (32, 2) : R^T [256 x 4096]
    dim3 gSm (DIM / 128, N_NODES / 128, 1);    // (2, 32) : XW_conv
    dim3 gTr(N_NODES / 32, DIM / 32);
    dim3 bTr(32, 8);
    dim3 gWt(DIM / 32, DIM / 32);
    const int NIT_SM = 3 * DIM / 64;           // 12
    const int SEG_SM = 2;
    int nbig8 = (int)((size_t)N_NODES * N_NODES / 8);
    int nx8   = N_NODES * DIM / 8;
    int nvec  = N_NODES * DIM / 4;

    // ---- fork ----
    cudaEventRecord(E0, 0);
    cudaStreamWaitEvent(s1, E0, 0);
    cudaStreamWaitEvent(s2, E0, 0);

    // s1: big matrix fp16 splits
    splith_kernel<<<nbig8 / 256, 256, 0, s1>>>((const float4*)d_inv, (uint4*)pDh, (uint4*)pDl, nbig8);
    cudaEventRecord(Ed, s1);
    splith_kernel<<<nbig8 / 256, 256, 0, s1>>>((const float4*)lap, (uint4*)pLh, (uint4*)pLl, nbig8);
    cudaEventRecord(El, s1);

    // s2: edges + CSR + W_conv; XW_conv GEMM; gather; init_out
    detect_init_kernel  <<<17, 256, 0, s2>>>((const unsigned int*)ei_raw);
    convert_edges_kernel<<<N_EDGES / 256, 256, 0, s2>>>(ei_raw);
    csr_scan_kernel     <<<1, 1024, 0, s2>>>();
    csr_place_kernel    <<<N_EDGES / 256, 256, 0, s2>>>();
    wtranspose_split_kernel<<<gWt, bTr, 0, s2>>>(W_conv, pWh2, pWl2);

    // s0: prologue — x splits first, then W_high^T
    split_kernel<<<nx8 / 256, 256>>>((const float4*)x, (uint4*)pXh, (uint4*)pXl, nx8);
    cudaEventRecord(Ex, 0);
    wtranspose_split_kernel<<<gWt, bTr>>>(W_high, pWh, pWl);

    // s2 continues
    cudaStreamWaitEvent(s2, Ex, 0);
    gemm_bf16_kernel<false><<<gSm, 128, GEMM_SMEM, s2>>>(pXh, pXl, pWh2, pWl2,
        pXWh, DIM, DIM, DIM, NIT_SM, SEG_SM);
    gather_kernel<<<N_NODES, 128, 0, s2>>>();
    init_out_kernel<<<(nvec + 255) / 256, 256, 0, s2>>>(out, b_conv, aL);
    cudaEventRecord(Ei, s2);

    // s0: R^T = relu(W_high^T @ x^T) -> fp16 plane g_Bf [256 x 4096]
    gemm_bf16_kernel<true><<<gRT, 128, GEMM_SMEM>>>(pWh, pWl, pXh, pXl,
        pBf, DIM, DIM, N_NODES, NIT_SM, SEG_SM);
    // T1 = d_inv @ R  (fp16 2-term GEMM, partials fp32 x1)
    cudaStreamWaitEvent(0, Ed, 0);
    gemm_f16_kernel<0><<<gBig, 128, GEMM_SMEM>>>(pDh, pDl, pBf,
        pP0, pP1, pP2, pP3, nullptr, nullptr, 1.0f);
    // B2 = (T1)/8 fp16
    transpose_sum4h_kernel<<<gTr, bTr>>>(pP0, pP1, pP2, pP3, pBf, 0.125f);
    // T2 = lap @ T1: acc = lap*(T1/8) -> store x8
    cudaStreamWaitEvent(0, El, 0);
    gemm_f16_kernel<0><<<gBig, 128, GEMM_SMEM>>>(pLh, pLl, pBf,
        pP0, pP1, pP2, pP3, nullptr, nullptr, 8.0f);
    // B3 = (T2)/64 fp16
    transpose_sum4h_kernel<<<gTr, bTr>>>(pP0, pP1, pP2, pP3, pBf, 0.015625f);
    // Hh: acc = d_inv*(T2/64); out += aH*64*acc  (out pre-set to aL*(Hl+b))
    cudaStreamWaitEvent(0, Ei, 0);
    gemm_f16_kernel<4><<<gBig, 128, GEMM_SMEM>>>(pDh, pDl, pBf,
        nullptr, nullptr, nullptr, nullptr, out, aH, 64.0f);

    cudaEventDestroy(E0); cudaEventDestroy(Ex); cudaEventDestroy(Ed);
    cudaEventDestroy(El); cudaEventDestroy(Ei);
    cudaStreamDestroy(s1); cudaStreamDestroy(s2);
}

// round 16
// speedup vs baseline: 5.1160x; 1.4939x over previous
#include <cuda_runtime.h>
#include <cuda_bf16.h>
#include <cuda_fp16.h>
#include <cstdint>

// FBGCN layer:
//   Hh = d_inv @ (lap @ (d_inv @ relu(x @ W_high)))
//     big GEMMs: single-fp16 A x single-fp16 B (K_eff = 4096)
//   Hl = GCNConv(x, edge_index, W_conv, b_conv)  -- CSR gather (fp16 features)
//   out = aL*Hl + aH*Hh (fused into GEMM3 atomic epilogue)

static constexpr int N_NODES = 4096;
static constexpr int DIM     = 256;
static constexpr int N_EDGES = 131072;

// fp32 scratch
__device__ __align__(16) float g_A[N_NODES * DIM];    // Hl
__device__ __align__(16) float g_P0[N_NODES * DIM];   // split-K partials
__device__ __align__(16) float g_P1[N_NODES * DIM];
__device__ __align__(16) float g_P2[N_NODES * DIM];
__device__ __align__(16) float g_P3[N_NODES * DIM];
__device__ __align__(16) __half g_XWh[N_NODES * DIM]; // XW_conv fp16 (gather)
__device__ float g_dis[N_NODES];
__device__ int   g_src[N_EDGES];
__device__ int   g_dst[N_EDGES];
__device__ int   g_is64;
// CSR
__device__ int   g_degi[N_NODES];
__device__ int   g_rowoff[N_NODES + 1];
__device__ int   g_cursor[N_NODES];
__device__ int   g_csr[N_EDGES];

// fp16 planes (big matrices) + activation
__device__ __align__(128) __half g_dinv_h[(size_t)N_NODES * N_NODES];
__device__ __align__(128) __half g_lap_h [(size_t)N_NODES * N_NODES];
__device__ __align__(128) __half g_Bf[DIM * N_NODES];       // act^T [256 x 4096] fp16

// bf16 buffers for the two small GEMMs
__device__ __align__(128) __nv_bfloat16 g_xhi[N_NODES * DIM];
__device__ __align__(128) __nv_bfloat16 g_xlo[N_NODES * DIM];
__device__ __align__(128) __nv_bfloat16 g_Wth[DIM * DIM];    // W_high^T splits
__device__ __align__(128) __nv_bfloat16 g_Wtl[DIM * DIM];
__device__ __align__(128) __nv_bfloat16 g_Wth2[DIM * DIM];   // W_conv^T splits
__device__ __align__(128) __nv_bfloat16 g_Wtl2[DIM * DIM];

// ---------------------------------------------------------------------------
// PTX helpers
// ---------------------------------------------------------------------------
__device__ __forceinline__ uint32_t smem_u32(const void* p) {
    uint32_t a;
    asm("{ .reg .u64 t; cvta.to.shared.u64 t, %1; cvt.u32.u64 %0, t; }" : "=r"(a) : "l"(p));
    return a;
}
__device__ __forceinline__ void cp_async16(uint32_t dst, const void* src) {
    asm volatile("cp.async.cg.shared.global [%0], [%1], 16;" :: "r"(dst), "l"(src) : "memory");
}
__device__ __forceinline__ void cp_commit() { asm volatile("cp.async.commit_group;" ::: "memory"); }
template <int N>
__device__ __forceinline__ void cp_wait() { asm volatile("cp.async.wait_group %0;" :: "n"(N) : "memory"); }

__device__ __forceinline__ void ldsm_x4(uint32_t* r, uint32_t addr) {
    asm volatile("ldmatrix.sync.aligned.m8n8.x4.shared.b16 {%0,%1,%2,%3}, [%4];"
        : "=r"(r[0]), "=r"(r[1]), "=r"(r[2]), "=r"(r[3]) : "r"(addr));
}
__device__ __forceinline__ void mma_bf16(float* c, const uint32_t* a, const uint32_t* b) {
    asm volatile("mma.sync.aligned.m16n8k16.row.col.f32.bf16.bf16.f32 "
        "{%0,%1,%2,%3}, {%4,%5,%6,%7}, {%8,%9}, {%0,%1,%2,%3};"
        : "+f"(c[0]), "+f"(c[1]), "+f"(c[2]), "+f"(c[3])
        : "r"(a[0]), "r"(a[1]), "r"(a[2]), "r"(a[3]), "r"(b[0]), "r"(b[1]));
}
__device__ __forceinline__ void mma_f16(float* c, const uint32_t* a, const uint32_t* b) {
    asm volatile("mma.sync.aligned.m16n8k16.row.col.f32.f16.f16.f32 "
        "{%0,%1,%2,%3}, {%4,%5,%6,%7}, {%8,%9}, {%0,%1,%2,%3};"
        : "+f"(c[0]), "+f"(c[1]), "+f"(c[2]), "+f"(c[3])
        : "r"(a[0]), "r"(a[1]), "r"(a[2]), "r"(a[3]), "r"(b[0]), "r"(b[1]));
}

// ---------------------------------------------------------------------------
// detect dtype + zero degree counters; edge convert + degree count
// ---------------------------------------------------------------------------
__global__ void detect_init_kernel(const unsigned int* __restrict__ raw)
{
    int b = blockIdx.x;
    if (b == 0) {
        if (threadIdx.x == 0) {
            int is64 = 1;
            #pragma unroll 1
            for (int i = 0; i < 128; i++)
                if (raw[2 * i + 1] != 0u) { is64 = 0; break; }
            g_is64 = is64;
        }
    } else {
        g_degi[(b - 1) * 256 + threadIdx.x] = 0;
    }
}
__global__ void convert_edges_kernel(const void* __restrict__ rawp)
{
    int e = blockIdx.x * blockDim.x + threadIdx.x;
    if (e >= N_EDGES) return;
    int s, d;
    if (g_is64) {
        const long long* ei = (const long long*)rawp;
        s = (int)ei[e];
        d = (int)ei[N_EDGES + e];
    } else {
        const int* ei = (const int*)rawp;
        s = ei[e];
        d = ei[N_EDGES + e];
    }
    g_src[e] = s;
    g_dst[e] = d;
    atomicAdd(&g_degi[d], 1);
}

// ---------------------------------------------------------------------------
// fp32 -> fp16 plane conversion (big matrices), 8 elems/thread
// ---------------------------------------------------------------------------
__global__ void cvt_h_kernel(const float4* __restrict__ src,
                             uint4* __restrict__ dst, int n8)
{
    int id = blockIdx.x * blockDim.x + threadIdx.x;
    if (id >= n8) return;
    float4 a = src[2 * id], b = src[2 * id + 1];
    __half2 h0 = __floats2half2_rn(a.x, a.y);
    __half2 h1 = __floats2half2_rn(a.z, a.w);
    __half2 h2 = __floats2half2_rn(b.x, b.y);
    __half2 h3 = __floats2half2_rn(b.z, b.w);
    dst[id] = make_uint4(*(uint32_t*)&h0, *(uint32_t*)&h1,
                         *(uint32_t*)&h2, *(uint32_t*)&h3);
}

// fp32 -> bf16 hi/lo split (x)
__global__ void split_kernel(const float4* __restrict__ src,
                             uint4* __restrict__ hi, uint4* __restrict__ lo, int n8)
{
    int id = blockIdx.x * blockDim.x + threadIdx.x;
    if (id >= n8) return;
    float4 a = src[2 * id], b = src[2 * id + 1];
    float f[8] = { a.x, a.y, a.z, a.w, b.x, b.y, b.z, b.w };
    uint32_t H[4], L[4];
    #pragma unroll
    for (int i = 0; i < 4; i++) {
        __nv_bfloat16 h0 = __float2bfloat16(f[2 * i + 0]);
        __nv_bfloat16 h1 = __float2bfloat16(f[2 * i + 1]);
        __nv_bfloat16 l0 = __float2bfloat16(f[2 * i + 0] - __bfloat162float(h0));
        __nv_bfloat16 l1 = __float2bfloat16(f[2 * i + 1] - __bfloat162float(h1));
        __nv_bfloat162 hh(h0, h1), ll(l0, l1);
        H[i] = *(uint32_t*)&hh;
        L[i] = *(uint32_t*)&ll;
    }
    hi[id] = make_uint4(H[0], H[1], H[2], H[3]);
    lo[id] = make_uint4(L[0], L[1], L[2], L[3]);
}

// ---------------------------------------------------------------------------
// sum 4 partials [4096 x 256] -> fp16 transposed [256 x 4096], scaled
// ---------------------------------------------------------------------------
__global__ void transpose_sum4h_kernel(const float* __restrict__ s0,
                                       const float* __restrict__ s1,
                                       const float* __restrict__ s2,
                                       const float* __restrict__ s3,
                                       __half* __restrict__ dst, float wScale)
{
    __shared__ float tile[32][33];
    int k0 = blockIdx.x * 32;
    int n0 = blockIdx.y * 32;
    int tx = threadIdx.x, ty = threadIdx.y;    // 32 x 8
    #pragma unroll
    for (int j = 0; j < 4; j++) {
        size_t o = (size_t)(k0 + ty + j * 8) * DIM + n0 + tx;
        tile[ty + j * 8][tx] = (s0[o] + s1[o]) + (s2[o] + s3[o]);
    }
    __syncthreads();
    #pragma unroll
    for (int j = 0; j < 4; j++) {
        int n = ty + j * 8;
        dst[(size_t)(n0 + n) * N_NODES + k0 + tx] = __float2half_rn(tile[tx][n] * wScale);
    }
}

// W [256 x 256] fp32 row-major -> W^T bf16 splits [256 x 256]
__global__ void wtranspose_split_kernel(const float* __restrict__ W,
                                        __nv_bfloat16* __restrict__ hi,
                                        __nv_bfloat16* __restrict__ lo)
{
    __shared__ float tile[32][33];
    int k0 = blockIdx.x * 32;
    int n0 = blockIdx.y * 32;
    int tx = threadIdx.x, ty = threadIdx.y;
    #pragma unroll
    for (int j = 0; j < 4; j++)
        tile[ty + j * 8][tx] = W[(size_t)(k0 + ty + j * 8) * DIM + n0 + tx];
    __syncthreads();
    #pragma unroll
    for (int j = 0; j < 4; j++) {
        int n = ty + j * 8;
        float v = tile[tx][n];
        __nv_bfloat16 h = __float2bfloat16(v);
        __nv_bfloat16 l = __float2bfloat16(v - __bfloat162float(h));
        size_t o = (size_t)(n0 + n) * DIM + k0 + tx;
        hi[o] = h; lo[o] = l;
    }
}

// ---------------------------------------------------------------------------
// Shared GEMM geometry
// ---------------------------------------------------------------------------
static constexpr int STAGES   = 3;
static constexpr int ROWB     = 144;
static constexpr int A_BYTES  = 128 * ROWB;
static constexpr int STAGE_B  = 2 * A_BYTES;
static constexpr int GEMM_SMEM = STAGES * STAGE_B;    // 110592

// ---------------------------------------------------------------------------
// bf16 3-term GEMM (small GEMMs): fp16 out (stride strideC)
// ---------------------------------------------------------------------------
template <bool RELU>
__global__ __launch_bounds__(128, 2) void gemm_bf16_kernel(
    const __nv_bfloat16* __restrict__ Ahi, const __nv_bfloat16* __restrict__ Alo,
    const __nv_bfloat16* __restrict__ Bhi, const __nv_bfloat16* __restrict__ Blo,
    __half* __restrict__ Ch,
    int strideA, int strideB, int strideC, int nit, int segShift)
{
    extern __shared__ char smem[];
    const uint32_t sbase = smem_u32(smem);
    const int t    = threadIdx.x;
    const int lane = t & 31;
    const int wid  = t >> 5;
    const int wm   = wid >> 1;
    const int wn   = wid & 1;
    const int m0   = blockIdx.y * 128;
    const int n0   = blockIdx.x * 128;
    const int segMask = (1 << segShift) - 1;

    const __nv_bfloat16* Aseg[3] = { Ahi, Ahi, Alo };
    const __nv_bfloat16* Bseg[3] = { Bhi, Blo, Bhi };

    const int rowBase = t >> 3;
    const int ch      = t & 7;
    uint32_t aOffG[8], bOffG[8], sOffA[8];
    #pragma unroll
    for (int i = 0; i < 8; i++) {
        int row = rowBase + 16 * i;
        aOffG[i] = (uint32_t)((m0 + row) * strideA + ch * 8);
        bOffG[i] = (uint32_t)((n0 + row) * strideB + ch * 8);
        sOffA[i] = (uint32_t)(row * ROWB + ch * 16);
    }
    const uint32_t aLd = (uint32_t)(wm * 64 + (lane & 15)) * ROWB + (lane >> 4) * 16;
    const uint32_t bLd = A_BYTES +
        (uint32_t)(wn * 64 + ((lane >> 4) & 1) * 8 + (lane & 7)) * ROWB + ((lane >> 3) & 1) * 16;

    float acc[4][8][4];
    #pragma unroll
    for (int f = 0; f < 4; f++)
        #pragma unroll
        for (int j = 0; j < 8; j++)
            #pragma unroll
            for (int e = 0; e < 4; e++) acc[f][j][e] = 0.f;

    auto load_stage = [&](int ci, int s) {
        if (ci < nit) {
            int seg = ci >> segShift;
            int k0  = (ci & segMask) << 6;
            const __nv_bfloat16* ap = Aseg[seg] + k0;
            const __nv_bfloat16* bp = Bseg[seg] + k0;
            uint32_t sb = sbase + s * STAGE_B;
            #pragma unroll
            for (int i = 0; i < 8; i++) cp_async16(sb + sOffA[i], ap + aOffG[i]);
            #pragma unroll
            for (int i = 0; i < 8; i++) cp_async16(sb + A_BYTES + sOffA[i], bp + bOffG[i]);
        }
        cp_commit();
    };

    load_stage(0, 0);
    load_stage(1, 1);

    for (int ci = 0; ci < nit; ci++) {
        cp_wait<STAGES - 2>();
        __syncthreads();
        load_stage(ci + STAGES - 1, (ci + STAGES - 1) % STAGES);

        uint32_t sb = sbase + (ci % STAGES) * STAGE_B;
        #pragma unroll
        for (int ks = 0; ks < 4; ks++) {
            uint32_t a[4][4], b[4][4];
            #pragma unroll
            for (int f = 0; f < 4; f++)
                ldsm_x4(a[f], sb + aLd + f * 16 * ROWB + ks * 32);
            #pragma unroll
            for (int g = 0; g < 4; g++)
                ldsm_x4(b[g], sb + bLd + g * 16 * ROWB + ks * 32);
            #pragma unroll
            for (int f = 0; f < 4; f++)
                #pragma unroll
                for (int g = 0; g < 4; g++) {
                    mma_bf16(acc[f][2 * g + 0], a[f], &b[g][0]);
                    mma_bf16(acc[f][2 * g + 1], a[f], &b[g][2]);
                }
        }
    }

    const int gid = lane >> 2;
    const int tig = lane & 3;
    #pragma unroll
    for (int f = 0; f < 4; f++) {
        int rbase = m0 + wm * 64 + f * 16 + gid;
        #pragma unroll
        for (int j = 0; j < 8; j++) {
            int col = n0 + wn * 64 + j * 8 + tig * 2;
            float2 v0 = { acc[f][j][0], acc[f][j][1] };
            float2 v1 = { acc[f][j][2], acc[f][j][3] };
            if (RELU) {
                v0.x = fmaxf(v0.x, 0.f); v0.y = fmaxf(v0.y, 0.f);
                v1.x = fmaxf(v1.x, 0.f); v1.y = fmaxf(v1.y, 0.f);
            }
            size_t o0 = (size_t)rbase * strideC + col;
            size_t o1 = (size_t)(rbase + 8) * strideC + col;
            __half2* Hp = (__half2*)Ch;
            Hp[o0 >> 1] = __floats2half2_rn(v0.x, v0.y);
            Hp[o1 >> 1] = __floats2half2_rn(v1.x, v1.y);
        }
    }
}

// ---------------------------------------------------------------------------
// fp16 GEMM (big GEMMs): single-plane A x single-plane B, K = 4096.
// split-K z=4, 16 iters each.
// OUT_MODE 0: fp32 x outScale to C0..C3.  OUT_MODE 4: atomicAdd(Out, aH*outScale*v).
// ---------------------------------------------------------------------------
template <int OUT_MODE>
__global__ __launch_bounds__(128, 2) void gemm_f16_kernel(
    const __half* __restrict__ A, const __half* __restrict__ B,
    float* __restrict__ C0, float* __restrict__ C1,
    float* __restrict__ C2, float* __restrict__ C3,
    float* __restrict__ OutAdd, const float* __restrict__ aHp, float outScale)
{
    extern __shared__ char smem[];
    const uint32_t sbase = smem_u32(smem);
    const int t    = threadIdx.x;
    const int lane = t & 31;
    const int wid  = t >> 5;
    const int wm   = wid >> 1;
    const int wn   = wid & 1;
    const int m0   = blockIdx.y * 128;
    const int n0   = blockIdx.x * 128;
    const int cBeg = blockIdx.z * 16;          // 16 iters per z, 64 total

    const int rowBase = t >> 3;
    const int ch      = t & 7;
    uint32_t aOffG[8], bOffG[8], sOffA[8];
    #pragma unroll
    for (int i = 0; i < 8; i++) {
        int row = rowBase + 16 * i;
        aOffG[i] = (uint32_t)((m0 + row) * N_NODES + ch * 8);
        bOffG[i] = (uint32_t)((n0 + row) * N_NODES + ch * 8);
        sOffA[i] = (uint32_t)(row * ROWB + ch * 16);
    }
    const uint32_t aLd = (uint32_t)(wm * 64 + (lane & 15)) * ROWB + (lane >> 4) * 16;
    const uint32_t bLd = A_BYTES +
        (uint32_t)(wn * 64 + ((lane >> 4) & 1) * 8 + (lane & 7)) * ROWB + ((lane >> 3) & 1) * 16;

    float acc[4][8][4];
    #pragma unroll
    for (int f = 0; f < 4; f++)
        #pragma unroll
        for (int j = 0; j < 8; j++)
            #pragma unroll
            for (int e = 0; e < 4; e++) acc[f][j][e] = 0.f;

    auto load_stage = [&](int ci, int s) {
        if (ci < 16) {
            int k0 = (cBeg + ci) << 6;
            const __half* ap = A + k0;
            const __half* bp = B + k0;
            uint32_t sb = sbase + s * STAGE_B;
            #pragma unroll
            for (int i = 0; i < 8; i++) cp_async16(sb + sOffA[i], ap + aOffG[i]);
            #pragma unroll
            for (int i = 0; i < 8; i++) cp_async16(sb + A_BYTES + sOffA[i], bp + bOffG[i]);
        }
        cp_commit();
    };

    load_stage(0, 0);
    load_stage(1, 1);

    for (int ci = 0; ci < 16; ci++) {
        cp_wait<STAGES - 2>();
        __syncthreads();
        load_stage(ci + STAGES - 1, (ci + STAGES - 1) % STAGES);

        uint32_t sb = sbase + (ci % STAGES) * STAGE_B;
        #pragma unroll
        for (int ks = 0; ks < 4; ks++) {
            uint32_t a[4][4], b[4][4];
            #pragma unroll
            for (int f = 0; f < 4; f++)
                ldsm_x4(a[f], sb + aLd + f * 16 * ROWB + ks * 32);
            #pragma unroll
            for (int g = 0; g < 4; g++)
                ldsm_x4(b[g], sb + bLd + g * 16 * ROWB + ks * 32);
            #pragma unroll
            for (int f = 0; f < 4; f++)
                #pragma unroll
                for (int g = 0; g < 4; g++) {
                    mma_f16(acc[f][2 * g + 0], a[f], &b[g][0]);
                    mma_f16(acc[f][2 * g + 1], a[f], &b[g][2]);
                }
        }
    }

    float* C = (blockIdx.z == 0) ? C0 : (blockIdx.z == 1) ? C1
             : (blockIdx.z == 2) ? C2 : C3;
    float sc = (OUT_MODE == 4) ? aHp[0] * outScale : outScale;
    const int gid = lane >> 2;
    const int tig = lane & 3;
    #pragma unroll
    for (int f = 0; f < 4; f++) {
        int rbase = m0 + wm * 64 + f * 16 + gid;
        #pragma unroll
        for (int j = 0; j < 8; j++) {
            int col = n0 + wn * 64 + j * 8 + tig * 2;
            float2 v0 = { acc[f][j][0] * sc, acc[f][j][1] * sc };
            float2 v1 = { acc[f][j][2] * sc, acc[f][j][3] * sc };
            size_t o0 = (size_t)rbase * DIM + col;
            size_t o1 = (size_t)(rbase + 8) * DIM + col;
            if (OUT_MODE == 4) {
                atomicAdd(OutAdd + o0 + 0, v0.x);
                atomicAdd(OutAdd + o0 + 1, v0.y);
                atomicAdd(OutAdd + o1 + 0, v1.x);
                atomicAdd(OutAdd + o1 + 1, v1.y);
            } else {
                *reinterpret_cast<float2*>(C + o0) = v0;
                *reinterpret_cast<float2*>(C + o1) = v1;
            }
        }
    }
}

// ---------------------------------------------------------------------------
// CSR build
// ---------------------------------------------------------------------------
__global__ __launch_bounds__(1024) void csr_scan_kernel()
{
    __shared__ int part[1024];
    int t = threadIdx.x;
    int v0 = g_degi[4 * t + 0], v1 = g_degi[4 * t + 1];
    int v2 = g_degi[4 * t + 2], v3 = g_degi[4 * t + 3];
    int s1 = v0 + v1, s2 = s1 + v2, s3 = s2 + v3;
    part[t] = s3;
    __syncthreads();
    #pragma unroll
    for (int off = 1; off < 1024; off <<= 1) {
        int x = (t >= off) ? part[t - off] : 0;
        __syncthreads();
        part[t] += x;
        __syncthreads();
    }
    int base = t ? part[t - 1] : 0;
    g_rowoff[4 * t + 0] = base;
    g_rowoff[4 * t + 1] = base + v0;
    g_rowoff[4 * t + 2] = base + s1;
    g_rowoff[4 * t + 3] = base + s2;
    if (t == 1023) g_rowoff[4096] = base + s3;
    #pragma unroll
    for (int i = 0; i < 4; i++) {
        int n = 4 * t + i;
        int d = g_degi[n];
        g_dis[n] = rsqrtf((float)(d + 1));
        g_cursor[n] = 0;
    }
}
__global__ void csr_place_kernel()
{
    int e = blockIdx.x * blockDim.x + threadIdx.x;
    if (e >= N_EDGES) return;
    int dst = g_dst[e];
    int pos = g_rowoff[dst] + atomicAdd(&g_cursor[dst], 1);
    g_csr[pos] = g_src[e];
}

// ---------------------------------------------------------------------------
// Gather: Hl[dst] -> g_A (side stream)
// ---------------------------------------------------------------------------
__global__ __launch_bounds__(128) void gather_kernel()
{
    int dst = blockIdx.x;
    int t   = threadIdx.x;
    const __half2* XW = (const __half2*)g_XWh;
    float disD = g_dis[dst];
    float2 sv = __half22float2(XW[(size_t)dst * 128 + t]);
    float accx = sv.x * disD * disD;
    float accy = sv.y * disD * disD;
    int beg = g_rowoff[dst], end = g_rowoff[dst + 1];
    int j = beg;
    for (; j + 1 < end; j += 2) {
        int s0 = g_csr[j], s1 = g_csr[j + 1];
        float w0 = g_dis[s0] * disD, w1 = g_dis[s1] * disD;
        float2 v0 = __half22float2(XW[(size_t)s0 * 128 + t]);
        float2 v1 = __half22float2(XW[(size_t)s1 * 128 + t]);
        accx += v0.x * w0 + v1.x * w1;
        accy += v0.y * w0 + v1.y * w1;
    }
    if (j < end) {
        int s0 = g_csr[j];
        float w0 = g_dis[s0] * disD;
        float2 v0 = __half22float2(XW[(size_t)s0 * 128 + t]);
        accx += v0.x * w0;
        accy += v0.y * w0;
    }
    *reinterpret_cast<float2*>(g_A + (size_t)dst * DIM + 2 * t) = make_float2(accx, accy);
}

// out = aL*(Hl + b)  (GEMM3 epilogue atomically adds aH*Hh on top)
__global__ void init_out_kernel(float* __restrict__ out,
                                const float* __restrict__ b,
                                const float* __restrict__ aLp)
{
    int id = blockIdx.x * blockDim.x + threadIdx.x;
    if (id >= N_NODES * DIM / 4) return;
    float aL = aLp[0];
    int c4 = (id & (DIM / 4 - 1)) << 2;
    float4 hl = reinterpret_cast<const float4*>(g_A)[id];
    float4 bb = *reinterpret_cast<const float4*>(b + c4);
    float4 r;
    r.x = aL * (hl.x + bb.x);
    r.y = aL * (hl.y + bb.y);
    r.z = aL * (hl.z + bb.z);
    r.w = aL * (hl.w + bb.w);
    reinterpret_cast<float4*>(out)[id] = r;
}

// ---------------------------------------------------------------------------
extern "C" void kernel_launch(void* const* d_in, const int* in_sizes, int n_in,
                              void* d_out, int out_size)
{
    const float* x      = (const float*)d_in[0];
    const void*  ei_raw = d_in[1];
    const float* lap    = (const float*)d_in[2];
    const float* d_inv  = (const float*)d_in[3];
    const float* W_high = (const float*)d_in[4];
    const float* W_conv = (const float*)d_in[5];
    const float* b_conv = (const float*)d_in[6];
    const float* aL     = (const float*)d_in[7];
    const float* aH     = (const float*)d_in[8];
    float*       out    = (float*)d_out;

    float *pP0, *pP1, *pP2, *pP3;
    cudaGetSymbolAddress((void**)&pP0, g_P0);
    cudaGetSymbolAddress((void**)&pP1, g_P1);
    cudaGetSymbolAddress((void**)&pP2, g_P2);
    cudaGetSymbolAddress((void**)&pP3, g_P3);
    __half *pXWh, *pDh, *pLh, *pBf;
    cudaGetSymbolAddress((void**)&pXWh, g_XWh);
    cudaGetSymbolAddress((void**)&pDh, g_dinv_h);
    cudaGetSymbolAddress((void**)&pLh, g_lap_h);
    cudaGetSymbolAddress((void**)&pBf, g_Bf);
    __nv_bfloat16 *pXh, *pXl, *pWh, *pWl, *pWh2, *pWl2;
    cudaGetSymbolAddress((void**)&pXh, g_xhi);
    cudaGetSymbolAddress((void**)&pXl, g_xlo);
    cudaGetSymbolAddress((void**)&pWh, g_Wth);
    cudaGetSymbolAddress((void**)&pWl, g_Wtl);
    cudaGetSymbolAddress((void**)&pWh2, g_Wth2);
    cudaGetSymbolAddress((void**)&pWl2, g_Wtl2);

    cudaFuncSetAttribute(gemm_bf16_kernel<false>, cudaFuncAttributeMaxDynamicSharedMemorySize, GEMM_SMEM);
    cudaFuncSetAttribute(gemm_bf16_kernel<true >, cudaFuncAttributeMaxDynamicSharedMemorySize, GEMM_SMEM);
    cudaFuncSetAttribute(gemm_f16_kernel<0>, cudaFuncAttributeMaxDynamicSharedMemorySize, GEMM_SMEM);
    cudaFuncSetAttribute(gemm_f16_kernel<4>, cudaFuncAttributeMaxDynamicSharedMemorySize, GEMM_SMEM);

    cudaStream_t s1, s2;
    cudaStreamCreateWithFlags(&s1, cudaStreamNonBlocking);
    cudaStreamCreateWithFlags(&s2, cudaStreamNonBlocking);
    cudaEvent_t E0, Ex, Ed, El, Ei;
    cudaEventCreateWithFlags(&E0, cudaEventDisableTiming);
    cudaEventCreateWithFlags(&Ex, cudaEventDisableTiming);
    cudaEventCreateWithFlags(&Ed, cudaEventDisableTiming);
    cudaEventCreateWithFlags(&El, cudaEventDisableTiming);
    cudaEventCreateWithFlags(&Ei, cudaEventDisableTiming);

    dim3 gBig(DIM / 128, N_NODES / 128, 4);    // (2, 32, 4)
    dim3 gRT (N_NODES / 128, DIM / 128, 1);    // (32, 2) : R^T [256 x 4096]
    dim3 gSm (DIM / 128, N_NODES / 128, 1);    // (2, 32) : XW_conv
    dim3 gTr(N_NODES / 32, DIM / 32);
    dim3 bTr(32, 8);
    dim3 gWt(DIM / 32, DIM / 32);
    const int NIT_SM = 3 * DIM / 64;           // 12
    const int SEG_SM = 2;
    int nbig8 = (int)((size_t)N_NODES * N_NODES / 8);
    int nx8   = N_NODES * DIM / 8;
    int nvec  = N_NODES * DIM / 4;

    // ---- fork ----
    cudaEventRecord(E0, 0);
    cudaStreamWaitEvent(s1, E0, 0);
    cudaStreamWaitEvent(s2, E0, 0);

    // s1: big matrix fp16 conversions
    cvt_h_kernel<<<nbig8 / 256, 256, 0, s1>>>((const float4*)d_inv, (uint4*)pDh, nbig8);
    cudaEventRecord(Ed, s1);
    cvt_h_kernel<<<nbig8 / 256, 256, 0, s1>>>((const float4*)lap, (uint4*)pLh, nbig8);
    cudaEventRecord(El, s1);

    // s2: edges + CSR + W_conv; XW_conv GEMM; gather; init_out
    detect_init_kernel  <<<17, 256, 0, s2>>>((const unsigned int*)ei_raw);
    convert_edges_kernel<<<N_EDGES / 256, 256, 0, s2>>>(ei_raw);
    csr_scan_kernel     <<<1, 1024, 0, s2>>>();
    csr_place_kernel    <<<N_EDGES / 256, 256, 0, s2>>>();
    wtranspose_split_kernel<<<gWt, bTr, 0, s2>>>(W_conv, pWh2, pWl2);

    // s0: prologue — x splits first, then W_high^T
    split_kernel<<<nx8 / 256, 256>>>((const float4*)x, (uint4*)pXh, (uint4*)pXl, nx8);
    cudaEventRecord(Ex, 0);
    wtranspose_split_kernel<<<gWt, bTr>>>(W_high, pWh, pWl);

    // s2 continues
    cudaStreamWaitEvent(s2, Ex, 0);
    gemm_bf16_kernel<false><<<gSm, 128, GEMM_SMEM, s2>>>(pXh, pXl, pWh2, pWl2,
        pXWh, DIM, DIM, DIM, NIT_SM, SEG_SM);
    gather_kernel<<<N_NODES, 128, 0, s2>>>();
    init_out_kernel<<<(nvec + 255) / 256, 256, 0, s2>>>(out, b_conv, aL);
    cudaEventRecord(Ei, s2);

    // s0: R^T = relu(W_high^T @ x^T) -> fp16 plane g_Bf [256 x 4096]
    gemm_bf16_kernel<true><<<gRT, 128, GEMM_SMEM>>>(pWh, pWl, pXh, pXl,
        pBf, DIM, DIM, N_NODES, NIT_SM, SEG_SM);
    // T1 = d_inv @ R
    cudaStreamWaitEvent(0, Ed, 0);
    gemm_f16_kernel<0><<<gBig, 128, GEMM_SMEM>>>(pDh, pBf,
        pP0, pP1, pP2, pP3, nullptr, nullptr, 1.0f);
    // B2 = (T1)/8 fp16
    transpose_sum4h_kernel<<<gTr, bTr>>>(pP0, pP1, pP2, pP3, pBf, 0.125f);
    // T2 = lap @ (T1/8) -> store x8
    cudaStreamWaitEvent(0, El, 0);
    gemm_f16_kernel<0><<<gBig, 128, GEMM_SMEM>>>(pLh, pBf,
        pP0, pP1, pP2, pP3, nullptr, nullptr, 8.0f);
    // B3 = (T2)/64 fp16
    transpose_sum4h_kernel<<<gTr, bTr>>>(pP0, pP1, pP2, pP3, pBf, 0.015625f);
    // Hh: acc = d_inv @ (T2/64); out += aH*64*acc  (out pre-set to aL*(Hl+b))
    cudaStreamWaitEvent(0, Ei, 0);
    gemm_f16_kernel<4><<<gBig, 128, GEMM_SMEM>>>(pDh, pBf,
        nullptr, nullptr, nullptr, nullptr, out, aH, 64.0f);

    cudaEventDestroy(E0); cudaEventDestroy(Ex); cudaEventDestroy(Ed);
    cudaEventDestroy(El); cudaEventDestroy(Ei);
    cudaStreamDestroy(s1); cudaStreamDestroy(s2);
}

// round 17
// speedup vs baseline: 5.6450x; 1.1034x over previous
#include <cuda_runtime.h>
#include <cuda_fp16.h>
#include <cstdint>

// FBGCN layer — all GEMMs in single-plane fp16 (legacy HMMA ceiling):
//   Hh = d_inv @ (lap @ (d_inv @ relu(x @ W_high)))
//   Hl = GCNConv(x, edge_index, W_conv, b_conv)  -- CSR gather (fp16 features)
//   out = aL*Hl + aH*Hh (fused into GEMM3 atomic epilogue)

static constexpr int N_NODES = 4096;
static constexpr int DIM     = 256;
static constexpr int N_EDGES = 131072;

// fp32 scratch
__device__ __align__(16) float g_A[N_NODES * DIM];    // Hl
__device__ __align__(16) float g_P0[N_NODES * DIM];   // split-K partials
__device__ __align__(16) float g_P1[N_NODES * DIM];
__device__ __align__(16) float g_P2[N_NODES * DIM];
__device__ __align__(16) float g_P3[N_NODES * DIM];
__device__ __align__(16) __half g_XWh[N_NODES * DIM]; // XW_conv fp16 (gather)
__device__ float g_dis[N_NODES];
__device__ int   g_src[N_EDGES];
__device__ int   g_dst[N_EDGES];
__device__ int   g_is64;
// CSR
__device__ int   g_degi[N_NODES];
__device__ int   g_rowoff[N_NODES + 1];
__device__ int   g_cursor[N_NODES];
__device__ int   g_csr[N_EDGES];

// fp16 planes
__device__ __align__(128) __half g_dinv_h[(size_t)N_NODES * N_NODES];
__device__ __align__(128) __half g_lap_h [(size_t)N_NODES * N_NODES];
__device__ __align__(128) __half g_Bf[DIM * N_NODES];   // act^T [256 x 4096]
__device__ __align__(128) __half g_xh[N_NODES * DIM];   // x fp16
__device__ __align__(128) __half g_Wt1[DIM * DIM];      // W_high^T fp16
__device__ __align__(128) __half g_Wt2[DIM * DIM];      // W_conv^T fp16

// ---------------------------------------------------------------------------
// PTX helpers
// ---------------------------------------------------------------------------
__device__ __forceinline__ uint32_t smem_u32(const void* p) {
    uint32_t a;
    asm("{ .reg .u64 t; cvta.to.shared.u64 t, %1; cvt.u32.u64 %0, t; }" : "=r"(a) : "l"(p));
    return a;
}
__device__ __forceinline__ void cp_async16(uint32_t dst, const void* src) {
    asm volatile("cp.async.cg.shared.global [%0], [%1], 16;" :: "r"(dst), "l"(src) : "memory");
}
__device__ __forceinline__ void cp_commit() { asm volatile("cp.async.commit_group;" ::: "memory"); }
template <int N>
__device__ __forceinline__ void cp_wait() { asm volatile("cp.async.wait_group %0;" :: "n"(N) : "memory"); }

__device__ __forceinline__ void ldsm_x4(uint32_t* r, uint32_t addr) {
    asm volatile("ldmatrix.sync.aligned.m8n8.x4.shared.b16 {%0,%1,%2,%3}, [%4];"
        : "=r"(r[0]), "=r"(r[1]), "=r"(r[2]), "=r"(r[3]) : "r"(addr));
}
__device__ __forceinline__ void mma_f16(float* c, const uint32_t* a, const uint32_t* b) {
    asm volatile("mma.sync.aligned.m16n8k16.row.col.f32.f16.f16.f32 "
        "{%0,%1,%2,%3}, {%4,%5,%6,%7}, {%8,%9}, {%0,%1,%2,%3};"
        : "+f"(c[0]), "+f"(c[1]), "+f"(c[2]), "+f"(c[3])
        : "r"(a[0]), "r"(a[1]), "r"(a[2]), "r"(a[3]), "r"(b[0]), "r"(b[1]));
}

// ---------------------------------------------------------------------------
// detect dtype + zero degree counters; edge convert + degree count
// ---------------------------------------------------------------------------
__global__ void detect_init_kernel(const unsigned int* __restrict__ raw)
{
    int b = blockIdx.x;
    if (b == 0) {
        if (threadIdx.x == 0) {
            int is64 = 1;
            #pragma unroll 1
            for (int i = 0; i < 128; i++)
                if (raw[2 * i + 1] != 0u) { is64 = 0; break; }
            g_is64 = is64;
        }
    } else {
        g_degi[(b - 1) * 256 + threadIdx.x] = 0;
    }
}
__global__ void convert_edges_kernel(const void* __restrict__ rawp)
{
    int e = blockIdx.x * blockDim.x + threadIdx.x;
    if (e >= N_EDGES) return;
    int s, d;
    if (g_is64) {
        const long long* ei = (const long long*)rawp;
        s = (int)ei[e];
        d = (int)ei[N_EDGES + e];
    } else {
        const int* ei = (const int*)rawp;
        s = ei[e];
        d = ei[N_EDGES + e];
    }
    g_src[e] = s;
    g_dst[e] = d;
    atomicAdd(&g_degi[d], 1);
}

// ---------------------------------------------------------------------------
// fp32 -> fp16 plane conversion, 8 elems/thread
// ---------------------------------------------------------------------------
__global__ void cvt_h_kernel(const float4* __restrict__ src,
                             uint4* __restrict__ dst, int n8)
{
    int id = blockIdx.x * blockDim.x + threadIdx.x;
    if (id >= n8) return;
    float4 a = src[2 * id], b = src[2 * id + 1];
    __half2 h0 = __floats2half2_rn(a.x, a.y);
    __half2 h1 = __floats2half2_rn(a.z, a.w);
    __half2 h2 = __floats2half2_rn(b.x, b.y);
    __half2 h3 = __floats2half2_rn(b.z, b.w);
    dst[id] = make_uint4(*(uint32_t*)&h0, *(uint32_t*)&h1,
                         *(uint32_t*)&h2, *(uint32_t*)&h3);
}

// W [256 x 256] fp32 row-major -> W^T fp16 [256 x 256]
__global__ void wtranspose_h_kernel(const float* __restrict__ W,
                                    __half* __restrict__ dst)
{
    __shared__ float tile[32][33];
    int k0 = blockIdx.x * 32;
    int n0 = blockIdx.y * 32;
    int tx = threadIdx.x, ty = threadIdx.y;    // 32 x 8
    #pragma unroll
    for (int j = 0; j < 4; j++)
        tile[ty + j * 8][tx] = W[(size_t)(k0 + ty + j * 8) * DIM + n0 + tx];
    __syncthreads();
    #pragma unroll
    for (int j = 0; j < 4; j++) {
        int n = ty + j * 8;
        dst[(size_t)(n0 + n) * DIM + k0 + tx] = __float2half_rn(tile[tx][n]);
    }
}

// sum 4 partials [4096 x 256] -> fp16 transposed [256 x 4096], scaled
__global__ void transpose_sum4h_kernel(const float* __restrict__ s0,
                                       const float* __restrict__ s1,
                                       const float* __restrict__ s2,
                                       const float* __restrict__ s3,
                                       __half* __restrict__ dst, float wScale)
{
    __shared__ float tile[32][33];
    int k0 = blockIdx.x * 32;
    int n0 = blockIdx.y * 32;
    int tx = threadIdx.x, ty = threadIdx.y;    // 32 x 8
    #pragma unroll
    for (int j = 0; j < 4; j++) {
        size_t o = (size_t)(k0 + ty + j * 8) * DIM + n0 + tx;
        tile[ty + j * 8][tx] = (s0[o] + s1[o]) + (s2[o] + s3[o]);
    }
    __syncthreads();
    #pragma unroll
    for (int j = 0; j < 4; j++) {
        int n = ty + j * 8;
        dst[(size_t)(n0 + n) * N_NODES + k0 + tx] = __float2half_rn(tile[tx][n] * wScale);
    }
}

// ---------------------------------------------------------------------------
// Unified fp16 GEMM: C[m][n] = sum_k A[m][k] * B[n][k].
// CTA 128x128, BK=64, 128 threads / 4 warps (2m x 2n), warp 64x64. 3-stage.
// Runtime: strideA, strideB, strideC, nit (iters per z; cBeg = z*nit).
// OUT_MODE 0: fp32 x outScale to C0..C3 (per z)
//          1: fp16 to Ch (+optional RELU)
//          4: atomicAdd(OutAdd, aH*outScale*v)
// ---------------------------------------------------------------------------
static constexpr int STAGES   = 3;
static constexpr int ROWB     = 144;
static constexpr int A_BYTES  = 128 * ROWB;
static constexpr int STAGE_B  = 2 * A_BYTES;
static constexpr int GEMM_SMEM = STAGES * STAGE_B;    // 110592

template <bool RELU, int OUT_MODE>
__global__ __launch_bounds__(128, 2) void gemm_f16_kernel(
    const __half* __restrict__ A, const __half* __restrict__ B,
    float* __restrict__ C0, float* __restrict__ C1,
    float* __restrict__ C2, float* __restrict__ C3,
    __half* __restrict__ Ch,
    float* __restrict__ OutAdd, const float* __restrict__ aHp, float outScale,
    int strideA, int strideB, int strideC, int nit)
{
    extern __shared__ char smem[];
    const uint32_t sbase = smem_u32(smem);
    const int t    = threadIdx.x;
    const int lane = t & 31;
    const int wid  = t >> 5;
    const int wm   = wid >> 1;
    const int wn   = wid & 1;
    const int m0   = blockIdx.y * 128;
    const int n0   = blockIdx.x * 128;
    const int cBeg = blockIdx.z * nit;

    const int rowBase = t >> 3;
    const int ch      = t & 7;
    uint32_t aOffG[8], bOffG[8], sOffA[8];
    #pragma unroll
    for (int i = 0; i < 8; i++) {
        int row = rowBase + 16 * i;
        aOffG[i] = (uint32_t)((m0 + row) * strideA + ch * 8);
        bOffG[i] = (uint32_t)((n0 + row) * strideB + ch * 8);
        sOffA[i] = (uint32_t)(row * ROWB + ch * 16);
    }
    const uint32_t aLd = (uint32_t)(wm * 64 + (lane & 15)) * ROWB + (lane >> 4) * 16;
    const uint32_t bLd = A_BYTES +
        (uint32_t)(wn * 64 + ((lane >> 4) & 1) * 8 + (lane & 7)) * ROWB + ((lane >> 3) & 1) * 16;

    float acc[4][8][4];
    #pragma unroll
    for (int f = 0; f < 4; f++)
        #pragma unroll
        for (int j = 0; j < 8; j++)
            #pragma unroll
            for (int e = 0; e < 4; e++) acc[f][j][e] = 0.f;

    auto load_stage = [&](int ci, int s) {
        if (ci < nit) {
            int k0 = (cBeg + ci) << 6;
            const __half* ap = A + k0;
            const __half* bp = B + k0;
            uint32_t sb = sbase + s * STAGE_B;
            #pragma unroll
            for (int i = 0; i < 8; i++) cp_async16(sb + sOffA[i], ap + aOffG[i]);
            #pragma unroll
            for (int i = 0; i < 8; i++) cp_async16(sb + A_BYTES + sOffA[i], bp + bOffG[i]);
        }
        cp_commit();
    };

    load_stage(0, 0);
    load_stage(1, 1);

    for (int ci = 0; ci < nit; ci++) {
        cp_wait<STAGES - 2>();
        __syncthreads();
        load_stage(ci + STAGES - 1, (ci + STAGES - 1) % STAGES);

        uint32_t sb = sbase + (ci % STAGES) * STAGE_B;
        #pragma unroll
        for (int ks = 0; ks < 4; ks++) {
            uint32_t a[4][4], b[4][4];
            #pragma unroll
            for (int f = 0; f < 4; f++)
                ldsm_x4(a[f], sb + aLd + f * 16 * ROWB + ks * 32);
            #pragma unroll
            for (int g = 0; g < 4; g++)
                ldsm_x4(b[g], sb + bLd + g * 16 * ROWB + ks * 32);
            #pragma unroll
            for (int f = 0; f < 4; f++)
                #pragma unroll
                for (int g = 0; g < 4; g++) {
                    mma_f16(acc[f][2 * g + 0], a[f], &b[g][0]);
                    mma_f16(acc[f][2 * g + 1], a[f], &b[g][2]);
                }
        }
    }

    float* C = (blockIdx.z == 0) ? C0 : (blockIdx.z == 1) ? C1
             : (blockIdx.z == 2) ? C2 : C3;
    float sc = (OUT_MODE == 4) ? aHp[0] * outScale : outScale;
    const int gid = lane >> 2;
    const int tig = lane & 3;
    #pragma unroll
    for (int f = 0; f < 4; f++) {
        int rbase = m0 + wm * 64 + f * 16 + gid;
        #pragma unroll
        for (int j = 0; j < 8; j++) {
            int col = n0 + wn * 64 + j * 8 + tig * 2;
            float2 v0 = { acc[f][j][0], acc[f][j][1] };
            float2 v1 = { acc[f][j][2], acc[f][j][3] };
            if (RELU) {
                v0.x = fmaxf(v0.x, 0.f); v0.y = fmaxf(v0.y, 0.f);
                v1.x = fmaxf(v1.x, 0.f); v1.y = fmaxf(v1.y, 0.f);
            }
            size_t o0 = (size_t)rbase * strideC + col;
            size_t o1 = (size_t)(rbase + 8) * strideC + col;
            if (OUT_MODE == 1) {
                __half2* Hp = (__half2*)Ch;
                Hp[o0 >> 1] = __floats2half2_rn(v0.x, v0.y);
                Hp[o1 >> 1] = __floats2half2_rn(v1.x, v1.y);
            } else if (OUT_MODE == 4) {
                atomicAdd(OutAdd + o0 + 0, sc * v0.x);
                atomicAdd(OutAdd + o0 + 1, sc * v0.y);
                atomicAdd(OutAdd + o1 + 0, sc * v1.x);
                atomicAdd(OutAdd + o1 + 1, sc * v1.y);
            } else {
                v0.x *= sc; v0.y *= sc; v1.x *= sc; v1.y *= sc;
                *reinterpret_cast<float2*>(C + o0) = v0;
                *reinterpret_cast<float2*>(C + o1) = v1;
            }
        }
    }
}

// ---------------------------------------------------------------------------
// CSR build
// ---------------------------------------------------------------------------
__global__ __launch_bounds__(1024) void csr_scan_kernel()
{
    __shared__ int part[1024];
    int t = threadIdx.x;
    int v0 = g_degi[4 * t + 0], v1 = g_degi[4 * t + 1];
    int v2 = g_degi[4 * t + 2], v3 = g_degi[4 * t + 3];
    int s1 = v0 + v1, s2 = s1 + v2, s3 = s2 + v3;
    part[t] = s3;
    __syncthreads();
    #pragma unroll
    for (int off = 1; off < 1024; off <<= 1) {
        int x = (t >= off) ? part[t - off] : 0;
        __syncthreads();
        part[t] += x;
        __syncthreads();
    }
    int base = t ? part[t - 1] : 0;
    g_rowoff[4 * t + 0] = base;
    g_rowoff[4 * t + 1] = base + v0;
    g_rowoff[4 * t + 2] = base + s1;
    g_rowoff[4 * t + 3] = base + s2;
    if (t == 1023) g_rowoff[4096] = base + s3;
    #pragma unroll
    for (int i = 0; i < 4; i++) {
        int n = 4 * t + i;
        int d = g_degi[n];
        g_dis[n] = rsqrtf((float)(d + 1));
        g_cursor[n] = 0;
    }
}
__global__ void csr_place_kernel()
{
    int e = blockIdx.x * blockDim.x + threadIdx.x;
    if (e >= N_EDGES) return;
    int dst = g_dst[e];
    int pos = g_rowoff[dst] + atomicAdd(&g_cursor[dst], 1);
    g_csr[pos] = g_src[e];
}

// ---------------------------------------------------------------------------
// Gather: Hl[dst] -> g_A (side stream)
// ---------------------------------------------------------------------------
__global__ __launch_bounds__(128) void gather_kernel()
{
    int dst = blockIdx.x;
    int t   = threadIdx.x;
    const __half2* XW = (const __half2*)g_XWh;
    float disD = g_dis[dst];
    float2 sv = __half22float2(XW[(size_t)dst * 128 + t]);
    float accx = sv.x * disD * disD;
    float accy = sv.y * disD * disD;
    int beg = g_rowoff[dst], end = g_rowoff[dst + 1];
    int j = beg;
    for (; j + 1 < end; j += 2) {
        int s0 = g_csr[j], s1 = g_csr[j + 1];
        float w0 = g_dis[s0] * disD, w1 = g_dis[s1] * disD;
        float2 v0 = __half22float2(XW[(size_t)s0 * 128 + t]);
        float2 v1 = __half22float2(XW[(size_t)s1 * 128 + t]);
        accx += v0.x * w0 + v1.x * w1;
        accy += v0.y * w0 + v1.y * w1;
    }
    if (j < end) {
        int s0 = g_csr[j];
        float w0 = g_dis[s0] * disD;
        float2 v0 = __half22float2(XW[(size_t)s0 * 128 + t]);
        accx += v0.x * w0;
        accy += v0.y * w0;
    }
    *reinterpret_cast<float2*>(g_A + (size_t)dst * DIM + 2 * t) = make_float2(accx, accy);
}

// out = aL*(Hl + b)  (GEMM3 epilogue atomically adds aH*Hh on top)
__global__ void init_out_kernel(float* __restrict__ out,
                                const float* __restrict__ b,
                                const float* __restrict__ aLp)
{
    int id = blockIdx.x * blockDim.x + threadIdx.x;
    if (id >= N_NODES * DIM / 4) return;
    float aL = aLp[0];
    int c4 = (id & (DIM / 4 - 1)) << 2;
    float4 hl = reinterpret_cast<const float4*>(g_A)[id];
    float4 bb = *reinterpret_cast<const float4*>(b + c4);
    float4 r;
    r.x = aL * (hl.x + bb.x);
    r.y = aL * (hl.y + bb.y);
    r.z = aL * (hl.z + bb.z);
    r.w = aL * (hl.w + bb.w);
    reinterpret_cast<float4*>(out)[id] = r;
}

// ---------------------------------------------------------------------------
extern "C" void kernel_launch(void* const* d_in, const int* in_sizes, int n_in,
                              void* d_out, int out_size)
{
    const float* x      = (const float*)d_in[0];
    const void*  ei_raw = d_in[1];
    const float* lap    = (const float*)d_in[2];
    const float* d_inv  = (const float*)d_in[3];
    const float* W_high = (const float*)d_in[4];
    const float* W_conv = (const float*)d_in[5];
    const float* b_conv = (const float*)d_in[6];
    const float* aL     = (const float*)d_in[7];
    const float* aH     = (const float*)d_in[8];
    float*       out    = (float*)d_out;

    float *pP0, *pP1, *pP2, *pP3;
    cudaGetSymbolAddress((void**)&pP0, g_P0);
    cudaGetSymbolAddress((void**)&pP1, g_P1);
    cudaGetSymbolAddress((void**)&pP2, g_P2);
    cudaGetSymbolAddress((void**)&pP3, g_P3);
    __half *pXWh, *pDh, *pLh, *pBf, *pXh, *pW1, *pW2;
    cudaGetSymbolAddress((void**)&pXWh, g_XWh);
    cudaGetSymbolAddress((void**)&pDh, g_dinv_h);
    cudaGetSymbolAddress((void**)&pLh, g_lap_h);
    cudaGetSymbolAddress((void**)&pBf, g_Bf);
    cudaGetSymbolAddress((void**)&pXh, g_xh);
    cudaGetSymbolAddress((void**)&pW1, g_Wt1);
    cudaGetSymbolAddress((void**)&pW2, g_Wt2);

    cudaFuncSetAttribute(gemm_f16_kernel<false, 0>, cudaFuncAttributeMaxDynamicSharedMemorySize, GEMM_SMEM);
    cudaFuncSetAttribute(gemm_f16_kernel<true,  1>, cudaFuncAttributeMaxDynamicSharedMemorySize, GEMM_SMEM);
    cudaFuncSetAttribute(gemm_f16_kernel<false, 1>, cudaFuncAttributeMaxDynamicSharedMemorySize, GEMM_SMEM);
    cudaFuncSetAttribute(gemm_f16_kernel<false, 4>, cudaFuncAttributeMaxDynamicSharedMemorySize, GEMM_SMEM);

    cudaStream_t s1, s2;
    cudaStreamCreateWithFlags(&s1, cudaStreamNonBlocking);
    cudaStreamCreateWithFlags(&s2, cudaStreamNonBlocking);
    cudaEvent_t E0, Ex, Ewh, Ed, El, Ei;
    cudaEventCreateWithFlags(&E0,  cudaEventDisableTiming);
    cudaEventCreateWithFlags(&Ex,  cudaEventDisableTiming);
    cudaEventCreateWithFlags(&Ewh, cudaEventDisableTiming);
    cudaEventCreateWithFlags(&Ed,  cudaEventDisableTiming);
    cudaEventCreateWithFlags(&El,  cudaEventDisableTiming);
    cudaEventCreateWithFlags(&Ei,  cudaEventDisableTiming);

    dim3 gBig(DIM / 128, N_NODES / 128, 4);    // (2, 32, 4): big GEMMs
    dim3 gRT (N_NODES / 128, DIM / 128, 1);    // (32, 2):  R^T [256 x 4096]
    dim3 gXW (DIM / 128, N_NODES / 128, 1);    // (2, 32):  XW_conv [4096 x 256]
    dim3 gTr(N_NODES / 32, DIM / 32);
    dim3 bTr(32, 8);
    dim3 gWt(DIM / 32, DIM / 32);
    int nbig8 = (int)((size_t)N_NODES * N_NODES / 8);
    int nx8   = N_NODES * DIM / 8;
    int nvec  = N_NODES * DIM / 4;

    // ---- fork ----
    cudaEventRecord(E0, 0);
    cudaStreamWaitEvent(s1, E0, 0);
    cudaStreamWaitEvent(s2, E0, 0);

    // s1: W_high^T fp16 (fast, gates R^T), then big matrix conversions
    wtranspose_h_kernel<<<gWt, bTr, 0, s1>>>(W_high, pW1);
    cudaEventRecord(Ewh, s1);
    cvt_h_kernel<<<nbig8 / 256, 256, 0, s1>>>((const float4*)d_inv, (uint4*)pDh, nbig8);
    cudaEventRecord(Ed, s1);
    cvt_h_kernel<<<nbig8 / 256, 256, 0, s1>>>((const float4*)lap, (uint4*)pLh, nbig8);
    cudaEventRecord(El, s1);

    // s2: edges + CSR + W_conv^T; XW_conv GEMM; gather; init_out
    detect_init_kernel  <<<17, 256, 0, s2>>>((const unsigned int*)ei_raw);
    convert_edges_kernel<<<N_EDGES / 256, 256, 0, s2>>>(ei_raw);
    csr_scan_kernel     <<<1, 1024, 0, s2>>>();
    csr_place_kernel    <<<N_EDGES / 256, 256, 0, s2>>>();
    wtranspose_h_kernel<<<gWt, bTr, 0, s2>>>(W_conv, pW2);

    // s0: x -> fp16
    cvt_h_kernel<<<nx8 / 256, 256>>>((const float4*)x, (uint4*)pXh, nx8);
    cudaEventRecord(Ex, 0);

    // s2 continues: XW_conv = x @ W_conv^T (fp16 out), gather, init_out
    cudaStreamWaitEvent(s2, Ex, 0);
    gemm_f16_kernel<false, 1><<<gXW, 128, GEMM_SMEM, s2>>>(pXh, pW2,
        nullptr, nullptr, nullptr, nullptr, pXWh, nullptr, nullptr, 1.0f,
        DIM, DIM, DIM, 4);
    gather_kernel<<<N_NODES, 128, 0, s2>>>();
    init_out_kernel<<<(nvec + 255) / 256, 256, 0, s2>>>(out, b_conv, aL);
    cudaEventRecord(Ei, s2);

    // s0: R^T = relu(W_high^T @ x^T) -> fp16 plane g_Bf [256 x 4096]
    cudaStreamWaitEvent(0, Ewh, 0);
    gemm_f16_kernel<true, 1><<<gRT, 128, GEMM_SMEM>>>(pW1, pXh,
        nullptr, nullptr, nullptr, nullptr, pBf, nullptr, nullptr, 1.0f,
        DIM, DIM, N_NODES, 4);
    // T1 = d_inv @ R
    cudaStreamWaitEvent(0, Ed, 0);
    gemm_f16_kernel<false, 0><<<gBig, 128, GEMM_SMEM>>>(pDh, pBf,
        pP0, pP1, pP2, pP3, nullptr, nullptr, nullptr, 1.0f,
        N_NODES, N_NODES, DIM, 16);
    // B2 = (T1)/8 fp16
    transpose_sum4h_kernel<<<gTr, bTr>>>(pP0, pP1, pP2, pP3, pBf, 0.125f);
    // T2 = lap @ (T1/8) -> store x8
    cudaStreamWaitEvent(0, El, 0);
    gemm_f16_kernel<false, 0><<<gBig, 128, GEMM_SMEM>>>(pLh, pBf,
        pP0, pP1, pP2, pP3, nullptr, nullptr, nullptr, 8.0f,
        N_NODES, N_NODES, DIM, 16);
    // B3 = (T2)/64 fp16
    transpose_sum4h_kernel<<<gTr, bTr>>>(pP0, pP1, pP2, pP3, pBf, 0.015625f);
    // Hh: acc = d_inv @ (T2/64); out += aH*64*acc  (out pre-set to aL*(Hl+b))
    cudaStreamWaitEvent(0, Ei, 0);
    gemm_f16_kernel<false, 4><<<gBig, 128, GEMM_SMEM>>>(pDh, pBf,
        nullptr, nullptr, nullptr, nullptr, nullptr, out, aH, 64.0f,
        N_NODES, N_NODES, DIM, 16);

    cudaEventDestroy(E0); cudaEventDestroy(Ex); cudaEventDestroy(Ewh);
    cudaEventDestroy(Ed); cudaEventDestroy(El); cudaEventDestroy(Ei);
    cudaStreamDestroy(s1); cudaStreamDestroy(s2);
}